// round 12
// baseline (speedup 1.0000x reference)
#include <cuda_runtime.h>
#include <cuda_fp16.h>
#include <stdint.h>

// Problem dims
#define BB   64
#define TT   4096
#define NTOK (BB*TT)          // 262144
#define TOKPC 128             // tokens per CTA
#define NCTAS (NTOK/TOKPC)    // 2048
#define NTHREADS 512

// smem strides (halves): row stride in 16B units coprime with 8 -> LDSM conflict-free
#define SC  104               // comb stride (K=96 padded)
#define SH  136               // weight stride (K=128 padded)
#define SHE 136               // hidden-exchange stride

// smem byte offsets
#define OFF_COMB   0                  // 128*SC*2  = 26624
#define OFF_HEXS   26624              // 128*SHE*2 = 34816
#define OFF_HEXT   61440              // 34816
#define OFF_WBS    96256              // 128*SH*2  = 34816
#define OFF_WBT    131072             // 34816
#define OFF_BIAS   165888             // 2048 halves = 4096
#define OFF_W2     169984             // 512 floats  = 2048
#define OFF_SPS    172032             // 256 floats  = 1024
#define OFF_SPT    173056             // 256 floats  = 1024
#define OFF_ZA     174080             // 128 floats  = 512
#define OFF_SRED   174592             // 128 floats  = 512
#define SMEM_TOT   175104

// ---------------- device scratch ----------------
__device__ __align__(16) __half g_wT[(size_t)BB * 64 * 64 * 64]; // [b][y][x][c] fp16, 32MB
__device__ __align__(16) __half g_wts[4 * 4 * 128 * 128];        // [net][layer][n][k] fp16
__device__ __align__(4) __half g_biasH[4 * 4 * 128];             // [net][layer][n] fp16
__device__ float g_part[NCTAS];                                  // per-tile s-sums (both passes)

// ---------------- helpers ----------------
__device__ __forceinline__ void mma16816(float c[4], const unsigned a0, const unsigned a1,
                                         const unsigned a2, const unsigned a3,
                                         unsigned b0, unsigned b1) {
    asm volatile(
        "mma.sync.aligned.m16n8k16.row.col.f32.f16.f16.f32 "
        "{%0,%1,%2,%3}, {%4,%5,%6,%7}, {%8,%9}, {%0,%1,%2,%3};"
        : "+f"(c[0]), "+f"(c[1]), "+f"(c[2]), "+f"(c[3])
        : "r"(a0), "r"(a1), "r"(a2), "r"(a3), "r"(b0), "r"(b1));
}

// f16-accumulate MMA: D fragment layout == aPack layout
__device__ __forceinline__ void mma16816h(unsigned c[2], const unsigned a0, const unsigned a1,
                                          const unsigned a2, const unsigned a3,
                                          unsigned b0, unsigned b1) {
    asm volatile(
        "mma.sync.aligned.m16n8k16.row.col.f16.f16.f16.f16 "
        "{%0,%1}, {%2,%3,%4,%5}, {%6,%7}, {%0,%1};"
        : "+r"(c[0]), "+r"(c[1])
        : "r"(a0), "r"(a1), "r"(a2), "r"(a3), "r"(b0), "r"(b1));
}

__device__ __forceinline__ void ldsm_x4(unsigned r[4], uint32_t addr) {
    asm volatile("ldmatrix.sync.aligned.m8n8.x4.shared.b16 {%0,%1,%2,%3}, [%4];"
                 : "=r"(r[0]), "=r"(r[1]), "=r"(r[2]), "=r"(r[3]) : "r"(addr));
}

__device__ __forceinline__ uint32_t smem_u32(const void* p) {
    uint32_t a;
    asm("{ .reg .u64 t; cvta.to.shared.u64 t, %1; cvt.u32.u64 %0, t; }" : "=r"(a) : "l"(p));
    return a;
}

__device__ __forceinline__ float fast_silu(float v) {
    float t;
    asm("tanh.approx.f32 %0, %1;" : "=f"(t) : "f"(0.5f * v));
    return 0.5f * v * (t + 1.0f);
}
__device__ __forceinline__ unsigned packh2(float a, float b) {
    __half2 h = __floats2half2_rn(a, b);
    return *(unsigned*)&h;
}
__device__ __forceinline__ __half2 silu_h2h(__half2 p) {
    __half2 u = __hmul2(p, __float2half2_rn(0.5f));
    __half2 t;
    asm("tanh.approx.f16x2 %0, %1;" : "=r"(*(unsigned*)&t) : "r"(*(unsigned*)&u));
    return __hfma2(u, t, u);
}

#define CP_ASYNC16(dst, src) \
    asm volatile("cp.async.cg.shared.global [%0], [%1], 16;" :: "r"(dst), "l"(src))
#define CP_COMMIT() asm volatile("cp.async.commit_group;" ::: "memory")
#define CP_WAIT0()  asm volatile("cp.async.wait_group 0;" ::: "memory")

// ---------------- transpose w[B,C,H,W] f32 -> wT[b][y][x][c] fp16 ----------------
__global__ void k_transpose(const float* __restrict__ w) {
    __shared__ float tile[64][65];
    int bid = blockIdx.x;
    int b = bid >> 6, y = bid & 63;
    int t = threadIdx.x;
    {
        int c = t >> 2, xq = (t & 3) * 16;
        const float4* src = (const float4*)(w + ((((b << 6) | c) << 6 | y) << 6) + xq);
#pragma unroll
        for (int j = 0; j < 4; j++) {
            float4 v = src[j];
            tile[c][xq + 4 * j + 0] = v.x;
            tile[c][xq + 4 * j + 1] = v.y;
            tile[c][xq + 4 * j + 2] = v.z;
            tile[c][xq + 4 * j + 3] = v.w;
        }
    }
    __syncthreads();
    {
        int xx = t >> 2, cq = (t & 3) * 16;
        __half2* dst = (__half2*)(g_wT + ((((size_t)(((b << 6) | y)) << 6 | xx)) << 6) + cq);
#pragma unroll
        for (int j = 0; j < 8; j++)
            dst[j] = __floats2half2_rn(tile[cq + 2 * j][xx], tile[cq + 2 * j + 1][xx]);
    }
}

// ---------------- pack weights (permuted cols: [lf 0..63 | cond 64..79 | z 80 | 0]) ----------------
__global__ void k_pack(const float* __restrict__ W0, const float* __restrict__ b0,
                       const float* __restrict__ W1, const float* __restrict__ b1) {
    int idx = blockIdx.x * 256 + threadIdx.x;
    int net = idx >> 16;
    int rem = idx & 65535;
    int layer = rem >> 14;
    int rem2 = rem & 16383;
    int n = rem2 >> 7, k = rem2 & 127;
    float v = 0.f;
    if (layer == 0) {
        int oc = -1;
        if (k < 64) oc = 1 + k;
        else if (k < 80) oc = 65 + (k - 64);
        else if (k == 80) oc = 0;
        if (oc >= 0) v = W0[(net * 128 + n) * 81 + oc];
    } else {
        v = W1[((net * 3 + (layer - 1)) * 128 + n) * 128 + k];
    }
    g_wts[idx] = __float2half_rn(v);
    if (idx < 2048) {
        int bn = idx >> 9, bl = (idx >> 7) & 3, bb_ = idx & 127;
        float bv = (bl == 0) ? b0[bn * 128 + bb_]
                             : b1[((bn * 3 + bl - 1) * 128) + bb_];
        g_biasH[idx] = __float2half_rn(bv);
    }
}

// ---------------- fused two-pass kernel: s-net and t-net in parallel warp groups ----------------
__global__ void __launch_bounds__(NTHREADS, 1) k_fused(
    const float* __restrict__ x, const float* __restrict__ cond,
    const float* __restrict__ W2, const float* __restrict__ b2,
    float* __restrict__ out) {
    extern __shared__ __align__(16) char smraw[];
    __half* combS  = (__half*)(smraw + OFF_COMB);
    __half* sbiasH = (__half*)(smraw + OFF_BIAS);
    float*  w2s    = (float*)(smraw + OFF_W2);
    float*  spartS = (float*)(smraw + OFF_SPS);
    float*  spartT = (float*)(smraw + OFF_SPT);
    float*  zA     = (float*)(smraw + OFF_ZA);
    float*  sred   = (float*)(smraw + OFF_SRED);

    int tid = threadIdx.x;
    int wid = tid >> 5, lane = tid & 31;
    int gid = lane >> 2, tig = lane & 3;
    int wg   = wid >> 3;         // 0 = s-net group, 1 = t-net group
    int wloc = wid & 7;
    int rowg = wloc & 3;         // 4 row-groups x 32 tokens = 128
    int colg = wloc >> 2;        // 2 col-groups x 64 cols
    int gtid = tid & 255;        // thread index within group
    int tile = blockIdx.x;

    uint32_t combA = smem_u32(combS);
    uint32_t hExG  = smem_u32(smraw + (wg ? OFF_HEXT : OFF_HEXS));
    uint32_t wbG   = smem_u32(smraw + (wg ? OFF_WBT : OFF_WBS));
    __half* hExP   = (__half*)(smraw + (wg ? OFF_HEXT : OFF_HEXS));

    // prefetch this group's pass-0 layer-0 weights (gi = wg*4)
    {
        const char* srcp = (const char*)g_wts + ((size_t)(wg * 4) << 15);
#pragma unroll
        for (int i = 0; i < 8; i++) {
            int ci = gtid + i * 256;
            int n = ci >> 4, q = ci & 15;
            CP_ASYNC16(wbG + (n * SH + q * 8) * 2, srcp + ci * 16);
        }
        CP_COMMIT();
    }

    // stage biases (all 16 layers) + w2 (all 4 nets)
    ((unsigned*)sbiasH)[tid]       = ((const unsigned*)g_biasH)[tid];
    ((unsigned*)sbiasH)[tid + 512] = ((const unsigned*)g_biasH)[tid + 512];
    w2s[tid] = __ldg(&W2[tid]);

    // ldmatrix per-thread offsets
    int aRow = lane & 15;
    int aK   = (lane >> 4) * 8;
    int bRow = (lane & 7) + ((lane >> 4) & 1) * 8;
    int bK   = ((lane >> 3) & 1) * 8;

    unsigned aPack[2][8][2];

    for (int ps = 0; ps < 2; ps++) {
        // ===== gather + build comb (4 threads per token) =====
        {
            int tk = tid >> 2, p = tid & 3;
            int g0 = tile * TOKPC + tk;
            int b = g0 >> 12;
            float zy = __ldg(&x[g0 * 2 + 1]);
            float zx = (ps == 0) ? __ldg(&x[g0 * 2]) : zA[tk];
            float zkeep = (ps == 0) ? zy : zx;
            float ix = zx * 63.f, iy = zy * 63.f;
            float ix0 = floorf(ix), iy0 = floorf(iy);
            float wx1 = ix - ix0, wx0 = 1.f - wx1;
            float wy1 = iy - iy0, wy0 = 1.f - wy1;
            float acc[16];
#pragma unroll
            for (int i = 0; i < 16; i++) acc[i] = 0.f;
            float cxs[4] = {ix0, ix0 + 1.f, ix0, ix0 + 1.f};
            float cys[4] = {iy0, iy0, iy0 + 1.f, iy0 + 1.f};
            float cws[4] = {wy0 * wx0, wy0 * wx1, wy1 * wx0, wy1 * wx1};
#pragma unroll
            for (int cr = 0; cr < 4; cr++) {
                float xf = cxs[cr], yf = cys[cr], wt = cws[cr];
                if (xf >= 0.f && xf <= 63.f && yf >= 0.f && yf <= 63.f) {
                    int xi = (int)xf, yi = (int)yf;
                    const __half2* src = (const __half2*)(
                        g_wT + ((((size_t)((b << 6) | yi) << 6 | xi)) << 6) + (p << 4));
#pragma unroll
                    for (int j = 0; j < 8; j++) {
                        float2 f = __half22float2(src[j]);
                        acc[2 * j]     += wt * f.x;
                        acc[2 * j + 1] += wt * f.y;
                    }
                }
            }
            __half* crow = combS + tk * SC;
            __half2* dst = (__half2*)crow + (p << 3);
#pragma unroll
            for (int j = 0; j < 8; j++) dst[j] = __floats2half2_rn(acc[2 * j], acc[2 * j + 1]);
            if (p == 0) {
#pragma unroll
                for (int i = 0; i < 16; i++)
                    crow[64 + i] = __float2half_rn(__ldg(&cond[b * 16 + i]));
                crow[80] = __float2half_rn(zkeep);
#pragma unroll
                for (int cc = 81; cc < 96; cc++) crow[cc] = __float2half_rn(0.f);
            }
        }
        CP_WAIT0();
        __syncthreads();   // comb + layer-0 weights visible

        // ===== 4 layer-phases of this pass (s and t nets concurrent) =====
        for (int l = 0; l < 4; l++) {
            int gi = ps * 8 + wg * 4 + l;          // g_wts layer index for this group
            uint32_t bb = wbG + ((64 * colg + bRow) * SH + bK) * 2;
            const __half* lbH = sbiasH + gi * 128 + 64 * colg;

            if (wg == 0) {
                // ================= s-net: fp32 accumulate =================
                float acc[2][8][4];
#pragma unroll
                for (int mt = 0; mt < 2; mt++)
#pragma unroll
                    for (int nt = 0; nt < 8; nt++)
#pragma unroll
                        for (int q = 0; q < 4; q++) acc[mt][nt][q] = 0.f;

                if (l == 0) {
                    uint32_t a0 = combA + ((32 * rowg + aRow) * SC + aK) * 2;
                    uint32_t a1 = a0 + 16 * SC * 2;
#pragma unroll
                    for (int ks = 0; ks < 6; ks++) {
                        unsigned af0[4], af1[4];
                        ldsm_x4(af0, a0 + ks * 32);
                        ldsm_x4(af1, a1 + ks * 32);
#pragma unroll
                        for (int ntp = 0; ntp < 4; ntp++) {
                            unsigned bf[4];
                            ldsm_x4(bf, bb + (ntp * 16 * SH) * 2 + ks * 32);
                            mma16816(acc[0][2 * ntp],     af0[0], af0[1], af0[2], af0[3], bf[0], bf[1]);
                            mma16816(acc[0][2 * ntp + 1], af0[0], af0[1], af0[2], af0[3], bf[2], bf[3]);
                            mma16816(acc[1][2 * ntp],     af1[0], af1[1], af1[2], af1[3], bf[0], bf[1]);
                            mma16816(acc[1][2 * ntp + 1], af1[0], af1[1], af1[2], af1[3], bf[2], bf[3]);
                        }
                    }
                } else {
                    int pc = colg ^ 1;
                    uint32_t pbase = hExG + ((32 * rowg + aRow) * SHE + 64 * pc + aK) * 2;
                    int pks0 = 4 * pc, oks0 = 4 * colg;
#pragma unroll
                    for (int q = 0; q < 4; q++) {
                        unsigned af0[4], af1[4];
                        ldsm_x4(af0, pbase + q * 32);
                        ldsm_x4(af1, pbase + 16 * SHE * 2 + q * 32);
#pragma unroll
                        for (int ntp = 0; ntp < 4; ntp++) {
                            unsigned bf[4];
                            ldsm_x4(bf, bb + (ntp * 16 * SH) * 2 + (pks0 + q) * 32);
                            mma16816(acc[0][2 * ntp],     af0[0], af0[1], af0[2], af0[3], bf[0], bf[1]);
                            mma16816(acc[0][2 * ntp + 1], af0[0], af0[1], af0[2], af0[3], bf[2], bf[3]);
                            mma16816(acc[1][2 * ntp],     af1[0], af1[1], af1[2], af1[3], bf[0], bf[1]);
                            mma16816(acc[1][2 * ntp + 1], af1[0], af1[1], af1[2], af1[3], bf[2], bf[3]);
                        }
                    }
#pragma unroll
                    for (int q = 0; q < 4; q++) {
#pragma unroll
                        for (int ntp = 0; ntp < 4; ntp++) {
                            unsigned bf[4];
                            ldsm_x4(bf, bb + (ntp * 16 * SH) * 2 + (oks0 + q) * 32);
                            mma16816(acc[0][2 * ntp], aPack[0][2 * q][0], aPack[0][2 * q][1],
                                     aPack[0][2 * q + 1][0], aPack[0][2 * q + 1][1], bf[0], bf[1]);
                            mma16816(acc[0][2 * ntp + 1], aPack[0][2 * q][0], aPack[0][2 * q][1],
                                     aPack[0][2 * q + 1][0], aPack[0][2 * q + 1][1], bf[2], bf[3]);
                            mma16816(acc[1][2 * ntp], aPack[1][2 * q][0], aPack[1][2 * q][1],
                                     aPack[1][2 * q + 1][0], aPack[1][2 * q + 1][1], bf[0], bf[1]);
                            mma16816(acc[1][2 * ntp + 1], aPack[1][2 * q][0], aPack[1][2 * q][1],
                                     aPack[1][2 * q + 1][0], aPack[1][2 * q + 1][1], bf[2], bf[3]);
                        }
                    }
                }

                __syncthreads();   // all wb/hEx/comb reads done (block-wide)

                // prefetch next phase weights for this group
                if (ps * 4 + l < 7) {
                    int phn = ps * 4 + l + 1;
                    int gin = (phn >> 2) * 8 + wg * 4 + (phn & 3);
                    const char* srcp = (const char*)g_wts + ((size_t)gin << 15);
#pragma unroll
                    for (int i = 0; i < 8; i++) {
                        int ci = gtid + i * 256;
                        int n = ci >> 4, q = ci & 15;
                        CP_ASYNC16(wbG + (n * SH + q * 8) * 2, srcp + ci * 16);
                    }
                    CP_COMMIT();
                }

                if (l == 3) {
                    const float* w2 = w2s + ps * 256 + 64 * colg;
#pragma unroll
                    for (int mt = 0; mt < 2; mt++) {
                        float p0 = 0.f, p1 = 0.f;
#pragma unroll
                        for (int nt = 0; nt < 8; nt++) {
                            int c = nt * 8 + tig * 2;
                            float2 bf2 = __half22float2(*(const __half2*)(lbH + c));
                            float w0 = w2[c], w1 = w2[c + 1];
                            p0 += fast_silu(acc[mt][nt][0] + bf2.x) * w0
                                + fast_silu(acc[mt][nt][1] + bf2.y) * w1;
                            p1 += fast_silu(acc[mt][nt][2] + bf2.x) * w0
                                + fast_silu(acc[mt][nt][3] + bf2.y) * w1;
                        }
                        p0 += __shfl_xor_sync(0xffffffffu, p0, 1);
                        p0 += __shfl_xor_sync(0xffffffffu, p0, 2);
                        p1 += __shfl_xor_sync(0xffffffffu, p1, 1);
                        p1 += __shfl_xor_sync(0xffffffffu, p1, 2);
                        if (tig == 0) {
                            spartS[colg * 128 + 32 * rowg + 16 * mt + gid]     = p0;
                            spartS[colg * 128 + 32 * rowg + 16 * mt + gid + 8] = p1;
                        }
                    }
                } else {
#pragma unroll
                    for (int mt = 0; mt < 2; mt++) {
                        __half* exb = hExP + (32 * rowg + 16 * mt + gid) * SHE + 64 * colg + tig * 2;
#pragma unroll
                        for (int nt = 0; nt < 8; nt++) {
                            float2 bf2 = __half22float2(*(const __half2*)(lbH + nt * 8 + tig * 2));
                            unsigned r0 = packh2(fast_silu(acc[mt][nt][0] + bf2.x),
                                                 fast_silu(acc[mt][nt][1] + bf2.y));
                            unsigned r1 = packh2(fast_silu(acc[mt][nt][2] + bf2.x),
                                                 fast_silu(acc[mt][nt][3] + bf2.y));
                            aPack[mt][nt][0] = r0;
                            aPack[mt][nt][1] = r1;
                            *(unsigned*)(exb + nt * 8)           = r0;
                            *(unsigned*)(exb + 8 * SHE + nt * 8) = r1;
                        }
                    }
                }
            } else {
                // ================= t-net: fp16 accumulate =================
                unsigned acch[2][8][2];
#pragma unroll
                for (int mt = 0; mt < 2; mt++)
#pragma unroll
                    for (int nt = 0; nt < 8; nt++) { acch[mt][nt][0] = 0u; acch[mt][nt][1] = 0u; }

                if (l == 0) {
                    uint32_t a0 = combA + ((32 * rowg + aRow) * SC + aK) * 2;
                    uint32_t a1 = a0 + 16 * SC * 2;
#pragma unroll
                    for (int ks = 0; ks < 6; ks++) {
                        unsigned af0[4], af1[4];
                        ldsm_x4(af0, a0 + ks * 32);
                        ldsm_x4(af1, a1 + ks * 32);
#pragma unroll
                        for (int ntp = 0; ntp < 4; ntp++) {
                            unsigned bf[4];
                            ldsm_x4(bf, bb + (ntp * 16 * SH) * 2 + ks * 32);
                            mma16816h(acch[0][2 * ntp],     af0[0], af0[1], af0[2], af0[3], bf[0], bf[1]);
                            mma16816h(acch[0][2 * ntp + 1], af0[0], af0[1], af0[2], af0[3], bf[2], bf[3]);
                            mma16816h(acch[1][2 * ntp],     af1[0], af1[1], af1[2], af1[3], bf[0], bf[1]);
                            mma16816h(acch[1][2 * ntp + 1], af1[0], af1[1], af1[2], af1[3], bf[2], bf[3]);
                        }
                    }
                } else {
                    int pc = colg ^ 1;
                    uint32_t pbase = hExG + ((32 * rowg + aRow) * SHE + 64 * pc + aK) * 2;
                    int pks0 = 4 * pc, oks0 = 4 * colg;
#pragma unroll
                    for (int q = 0; q < 4; q++) {
                        unsigned af0[4], af1[4];
                        ldsm_x4(af0, pbase + q * 32);
                        ldsm_x4(af1, pbase + 16 * SHE * 2 + q * 32);
#pragma unroll
                        for (int ntp = 0; ntp < 4; ntp++) {
                            unsigned bf[4];
                            ldsm_x4(bf, bb + (ntp * 16 * SH) * 2 + (pks0 + q) * 32);
                            mma16816h(acch[0][2 * ntp],     af0[0], af0[1], af0[2], af0[3], bf[0], bf[1]);
                            mma16816h(acch[0][2 * ntp + 1], af0[0], af0[1], af0[2], af0[3], bf[2], bf[3]);
                            mma16816h(acch[1][2 * ntp],     af1[0], af1[1], af1[2], af1[3], bf[0], bf[1]);
                            mma16816h(acch[1][2 * ntp + 1], af1[0], af1[1], af1[2], af1[3], bf[2], bf[3]);
                        }
                    }
#pragma unroll
                    for (int q = 0; q < 4; q++) {
#pragma unroll
                        for (int ntp = 0; ntp < 4; ntp++) {
                            unsigned bf[4];
                            ldsm_x4(bf, bb + (ntp * 16 * SH) * 2 + (oks0 + q) * 32);
                            mma16816h(acch[0][2 * ntp], aPack[0][2 * q][0], aPack[0][2 * q][1],
                                      aPack[0][2 * q + 1][0], aPack[0][2 * q + 1][1], bf[0], bf[1]);
                            mma16816h(acch[0][2 * ntp + 1], aPack[0][2 * q][0], aPack[0][2 * q][1],
                                      aPack[0][2 * q + 1][0], aPack[0][2 * q + 1][1], bf[2], bf[3]);
                            mma16816h(acch[1][2 * ntp], aPack[1][2 * q][0], aPack[1][2 * q][1],
                                      aPack[1][2 * q + 1][0], aPack[1][2 * q + 1][1], bf[0], bf[1]);
                            mma16816h(acch[1][2 * ntp + 1], aPack[1][2 * q][0], aPack[1][2 * q][1],
                                      aPack[1][2 * q + 1][0], aPack[1][2 * q + 1][1], bf[2], bf[3]);
                        }
                    }
                }

                __syncthreads();   // all wb/hEx/comb reads done (block-wide)

                if (ps * 4 + l < 7) {
                    int phn = ps * 4 + l + 1;
                    int gin = (phn >> 2) * 8 + wg * 4 + (phn & 3);
                    const char* srcp = (const char*)g_wts + ((size_t)gin << 15);
#pragma unroll
                    for (int i = 0; i < 8; i++) {
                        int ci = gtid + i * 256;
                        int n = ci >> 4, q = ci & 15;
                        CP_ASYNC16(wbG + (n * SH + q * 8) * 2, srcp + ci * 16);
                    }
                    CP_COMMIT();
                }

                if (l == 3) {
                    const float* w2 = w2s + ps * 256 + 128 + 64 * colg;
#pragma unroll
                    for (int mt = 0; mt < 2; mt++) {
                        float p0 = 0.f, p1 = 0.f;
#pragma unroll
                        for (int nt = 0; nt < 8; nt++) {
                            int c = nt * 8 + tig * 2;
                            __half2 bias = *(const __half2*)(lbH + c);
                            float w0 = w2[c], w1 = w2[c + 1];
                            float2 f0 = __half22float2(silu_h2h(__hadd2(*(__half2*)&acch[mt][nt][0], bias)));
                            float2 f1 = __half22float2(silu_h2h(__hadd2(*(__half2*)&acch[mt][nt][1], bias)));
                            p0 += f0.x * w0 + f0.y * w1;
                            p1 += f1.x * w0 + f1.y * w1;
                        }
                        p0 += __shfl_xor_sync(0xffffffffu, p0, 1);
                        p0 += __shfl_xor_sync(0xffffffffu, p0, 2);
                        p1 += __shfl_xor_sync(0xffffffffu, p1, 1);
                        p1 += __shfl_xor_sync(0xffffffffu, p1, 2);
                        if (tig == 0) {
                            spartT[colg * 128 + 32 * rowg + 16 * mt + gid]     = p0;
                            spartT[colg * 128 + 32 * rowg + 16 * mt + gid + 8] = p1;
                        }
                    }
                } else {
#pragma unroll
                    for (int mt = 0; mt < 2; mt++) {
                        __half* exb = hExP + (32 * rowg + 16 * mt + gid) * SHE + 64 * colg + tig * 2;
#pragma unroll
                        for (int nt = 0; nt < 8; nt++) {
                            __half2 bias = *(const __half2*)(lbH + nt * 8 + tig * 2);
                            __half2 h0 = silu_h2h(__hadd2(*(__half2*)&acch[mt][nt][0], bias));
                            __half2 h1 = silu_h2h(__hadd2(*(__half2*)&acch[mt][nt][1], bias));
                            unsigned r0 = *(unsigned*)&h0;
                            unsigned r1 = *(unsigned*)&h1;
                            aPack[mt][nt][0] = r0;
                            aPack[mt][nt][1] = r1;
                            *(unsigned*)(exb + nt * 8)           = r0;
                            *(unsigned*)(exb + 8 * SHE + nt * 8) = r1;
                        }
                    }
                }
            }

            CP_WAIT0();
            __syncthreads();   // next weights ready + hEx writes visible
        }

        // ===== coupling epilogue for this pass =====
        if (tid < TOKPC) {
            int g0 = tile * TOKPC + tid;
            float zold = (ps == 0) ? __ldg(&x[g0 * 2]) : __ldg(&x[g0 * 2 + 1]);
            float s_lin = spartS[tid] + spartS[128 + tid] + __ldg(&b2[ps * 2]);
            float t_lin = spartT[tid] + spartT[128 + tid] + __ldg(&b2[ps * 2 + 1]);
            float sv = tanhf(s_lin) * 1.5f;
            float z = zold * __expf(sv) + t_lin;
            out[g0 * 2 + ps] = z;
            if (ps == 0) { zA[tid] = z; sred[tid] = sv; }
            else sred[tid] += sv;
        }
        __syncthreads();
    }

    // ===== deterministic block reduce of s (both passes) =====
    if (tid < 64) sred[tid] += sred[tid + 64];
    __syncthreads();
    if (tid < 32) {
        float v = sred[tid] + sred[tid + 32];
#pragma unroll
        for (int off = 16; off; off >>= 1) v += __shfl_xor_sync(0xffffffffu, v, off);
        if (tid == 0) g_part[tile] = v;
    }
}

// ---------------- log-det reduce ----------------
__global__ void k_reduce(float* __restrict__ out) {
    int b = threadIdx.x;
    if (b < BB) {
        float acc = 0.f;
        for (int i = 0; i < 32; i++)
            acc += g_part[b * 32 + i];
        out[(size_t)NTOK * 2 + b] = acc;
    }
}

// ---------------- launcher ----------------
extern "C" void kernel_launch(void* const* d_in, const int* in_sizes, int n_in,
                              void* d_out, int out_size) {
    const float* x    = (const float*)d_in[0];
    const float* w    = (const float*)d_in[1];
    const float* cond = (const float*)d_in[2];
    const float* W0   = (const float*)d_in[3];
    const float* b0   = (const float*)d_in[4];
    const float* W1   = (const float*)d_in[5];
    const float* b1   = (const float*)d_in[6];
    const float* W2   = (const float*)d_in[7];
    const float* b2   = (const float*)d_in[8];
    float* out = (float*)d_out;

    cudaFuncSetAttribute(k_fused, cudaFuncAttributeMaxDynamicSharedMemorySize, SMEM_TOT);

    k_transpose<<<4096, 256>>>(w);
    k_pack<<<1024, 256>>>(W0, b0, W1, b1);
    k_fused<<<NCTAS, NTHREADS, SMEM_TOT>>>(x, cond, W2, b2, out);
    k_reduce<<<1, 64>>>(out);
}

// round 13
// speedup vs baseline: 1.2173x; 1.2173x over previous
#include <cuda_runtime.h>
#include <cuda_fp16.h>
#include <stdint.h>

// Problem dims
#define BB   64
#define TT   4096
#define NTOK (BB*TT)          // 262144
#define TOKPC 128             // tokens per CTA
#define NCTAS (NTOK/TOKPC)    // 2048
#define NTHREADS 256

// smem strides (halves): row stride in 16B units coprime with 8 -> LDSM conflict-free
#define SC  104               // comb stride (K=96 padded)
#define SHE 136               // hidden-exchange stride

// smem byte offsets
#define OFF_COMB   0                  // 128*SC*2  = 26624
#define OFF_HEX0   26624              // 128*SHE*2 = 34816
#define OFF_HEX1   61440              // 34816
#define OFF_BIAS   96256              // 2048 halves = 4096
#define OFF_W2     100352             // 512 floats  = 2048
#define OFF_SPS    102400             // 256 floats  = 1024
#define OFF_SPT    103424             // 256 floats  = 1024
#define OFF_ZA     104448             // 128 floats  = 512
#define OFF_SRED   104960             // 128 floats  = 512
#define SMEM_TOT   105472

// ---------------- device scratch ----------------
__device__ __align__(16) __half g_wT[(size_t)BB * 64 * 64 * 64]; // [b][y][x][c] fp16, 32MB
__device__ __align__(16) uint4 g_wfrag[16 * 2048];               // [li][colg][ntp][ks][lane] frag words, 512KB
__device__ __align__(4) __half g_biasH[4 * 4 * 128];             // [net][layer][n] fp16
__device__ float g_part[NCTAS];                                  // per-tile s-sums (both passes)

// ---------------- helpers ----------------
__device__ __forceinline__ void mma16816(float c[4], const unsigned a0, const unsigned a1,
                                         const unsigned a2, const unsigned a3,
                                         unsigned b0, unsigned b1) {
    asm volatile(
        "mma.sync.aligned.m16n8k16.row.col.f32.f16.f16.f32 "
        "{%0,%1,%2,%3}, {%4,%5,%6,%7}, {%8,%9}, {%0,%1,%2,%3};"
        : "+f"(c[0]), "+f"(c[1]), "+f"(c[2]), "+f"(c[3])
        : "r"(a0), "r"(a1), "r"(a2), "r"(a3), "r"(b0), "r"(b1));
}

// f16-accumulate MMA: D fragment layout == aPack layout
__device__ __forceinline__ void mma16816h(unsigned c[2], const unsigned a0, const unsigned a1,
                                          const unsigned a2, const unsigned a3,
                                          unsigned b0, unsigned b1) {
    asm volatile(
        "mma.sync.aligned.m16n8k16.row.col.f16.f16.f16.f16 "
        "{%0,%1}, {%2,%3,%4,%5}, {%6,%7}, {%0,%1};"
        : "+r"(c[0]), "+r"(c[1])
        : "r"(a0), "r"(a1), "r"(a2), "r"(a3), "r"(b0), "r"(b1));
}

__device__ __forceinline__ void ldsm_x4(unsigned r[4], uint32_t addr) {
    asm volatile("ldmatrix.sync.aligned.m8n8.x4.shared.b16 {%0,%1,%2,%3}, [%4];"
                 : "=r"(r[0]), "=r"(r[1]), "=r"(r[2]), "=r"(r[3]) : "r"(addr));
}

__device__ __forceinline__ uint32_t smem_u32(const void* p) {
    uint32_t a;
    asm("{ .reg .u64 t; cvta.to.shared.u64 t, %1; cvt.u32.u64 %0, t; }" : "=r"(a) : "l"(p));
    return a;
}

__device__ __forceinline__ float fast_silu(float v) {
    float t;
    asm("tanh.approx.f32 %0, %1;" : "=f"(t) : "f"(0.5f * v));
    return 0.5f * v * (t + 1.0f);
}
__device__ __forceinline__ unsigned packh2(float a, float b) {
    __half2 h = __floats2half2_rn(a, b);
    return *(unsigned*)&h;
}
__device__ __forceinline__ __half2 silu_h2h(__half2 p) {
    __half2 u = __hmul2(p, __float2half2_rn(0.5f));
    __half2 t;
    asm("tanh.approx.f16x2 %0, %1;" : "=r"(*(unsigned*)&t) : "r"(*(unsigned*)&u));
    return __hfma2(u, t, u);
}

// ---------------- transpose w[B,C,H,W] f32 -> wT[b][y][x][c] fp16 ----------------
__global__ void k_transpose(const float* __restrict__ w) {
    __shared__ float tile[64][65];
    int bid = blockIdx.x;
    int b = bid >> 6, y = bid & 63;
    int t = threadIdx.x;
    {
        int c = t >> 2, xq = (t & 3) * 16;
        const float4* src = (const float4*)(w + ((((b << 6) | c) << 6 | y) << 6) + xq);
#pragma unroll
        for (int j = 0; j < 4; j++) {
            float4 v = src[j];
            tile[c][xq + 4 * j + 0] = v.x;
            tile[c][xq + 4 * j + 1] = v.y;
            tile[c][xq + 4 * j + 2] = v.z;
            tile[c][xq + 4 * j + 3] = v.w;
        }
    }
    __syncthreads();
    {
        int xx = t >> 2, cq = (t & 3) * 16;
        __half2* dst = (__half2*)(g_wT + ((((size_t)(((b << 6) | y)) << 6 | xx)) << 6) + cq);
#pragma unroll
        for (int j = 0; j < 8; j++)
            dst[j] = __floats2half2_rn(tile[cq + 2 * j][xx], tile[cq + 2 * j + 1][xx]);
    }
}

// ---------------- pack weights into MMA B-fragment order ----------------
// g_wfrag[li*2048 + ((colg*4+ntp)*8+ks)*32 + lane] = {b0,b1} for nt=2ntp, {b0,b1} for nt=2ntp+1
// li = net*4+layer; col permutation for layer 0: [lf 0..63 | cond 64..79 | z 80 | 0 pad to 128]
__device__ __forceinline__ float getw_(const float* W0, const float* W1,
                                       int net, int layer, int n, int k) {
    if (layer == 0) {
        int oc = -1;
        if (k < 64) oc = 1 + k;
        else if (k < 80) oc = 65 + (k - 64);
        else if (k == 80) oc = 0;
        return (oc >= 0) ? W0[(net * 128 + n) * 81 + oc] : 0.f;
    }
    return W1[((net * 3 + (layer - 1)) * 128 + n) * 128 + k];
}

__global__ void k_packfrag(const float* __restrict__ W0, const float* __restrict__ b0,
                           const float* __restrict__ W1, const float* __restrict__ b1) {
    int idx = blockIdx.x * 256 + threadIdx.x;      // 0..32767
    int gi = idx >> 11;
    int rem = idx & 2047;
    int lane = rem & 31;
    int ks = (rem >> 5) & 7;
    int ntp = (rem >> 8) & 3;
    int colg = (rem >> 10) & 1;
    int net = gi >> 2, layer = gi & 3;
    int gid = lane >> 2, tig = lane & 3;
    int n_even = colg * 64 + ntp * 16 + gid;
    int n_odd  = n_even + 8;
    int k0 = ks * 16 + tig * 2;
    uint4 v;
    v.x = packh2(getw_(W0, W1, net, layer, n_even, k0),     getw_(W0, W1, net, layer, n_even, k0 + 1));
    v.y = packh2(getw_(W0, W1, net, layer, n_even, k0 + 8), getw_(W0, W1, net, layer, n_even, k0 + 9));
    v.z = packh2(getw_(W0, W1, net, layer, n_odd,  k0),     getw_(W0, W1, net, layer, n_odd,  k0 + 1));
    v.w = packh2(getw_(W0, W1, net, layer, n_odd,  k0 + 8), getw_(W0, W1, net, layer, n_odd,  k0 + 9));
    g_wfrag[idx] = v;
    if (idx < 2048) {
        int bn = idx >> 9, bl = (idx >> 7) & 3, bb_ = idx & 127;
        float bv = (bl == 0) ? b0[bn * 128 + bb_]
                             : b1[((bn * 3 + bl - 1) * 128) + bb_];
        g_biasH[idx] = __float2half_rn(bv);
    }
}

// ---------------- fused two-pass coupling kernel (weights via LDG fragments) ----------------
__global__ void __launch_bounds__(NTHREADS, 2) k_fused(
    const float* __restrict__ x, const float* __restrict__ cond,
    const float* __restrict__ W2, const float* __restrict__ b2,
    float* __restrict__ out) {
    extern __shared__ __align__(16) char smraw[];
    __half* combS  = (__half*)(smraw + OFF_COMB);
    __half* sbiasH = (__half*)(smraw + OFF_BIAS);
    float*  w2s    = (float*)(smraw + OFF_W2);
    float*  spartS = (float*)(smraw + OFF_SPS);
    float*  spartT = (float*)(smraw + OFF_SPT);
    float*  zA     = (float*)(smraw + OFF_ZA);
    float*  sred   = (float*)(smraw + OFF_SRED);

    int tid = threadIdx.x;
    int wid = tid >> 5, lane = tid & 31;
    int gid = lane >> 2, tig = lane & 3;
    int rowg = wid & 3;          // 4 row-groups x 32 tokens = 128
    int colg = wid >> 2;         // 2 col-groups x 64 cols
    int tile = blockIdx.x;

    uint32_t combA = smem_u32(combS);
    uint32_t hexA[2] = {smem_u32(smraw + OFF_HEX0), smem_u32(smraw + OFF_HEX1)};
    __half* hexP[2] = {(__half*)(smraw + OFF_HEX0), (__half*)(smraw + OFF_HEX1)};

    // stage biases (all 16 layers) + w2 (all 4 nets)
#pragma unroll
    for (int i = 0; i < 4; i++)
        ((unsigned*)sbiasH)[tid + i * 256] = ((const unsigned*)g_biasH)[tid + i * 256];
    w2s[tid] = __ldg(&W2[tid]);
    w2s[tid + 256] = __ldg(&W2[tid + 256]);

    // ldmatrix per-thread offsets
    int aRow = lane & 15;
    int aK   = (lane >> 4) * 8;

    unsigned aPack[2][8][2];
    int lastw = 1;   // hEx ping-pong: next write goes to lastw^1

    for (int ps = 0; ps < 2; ps++) {
        // ===== gather + build comb (2 threads per token) =====
        {
            int tk = tid >> 1, p = tid & 1;
            int g0 = tile * TOKPC + tk;
            int b = g0 >> 12;
            float zy = __ldg(&x[g0 * 2 + 1]);
            float zx = (ps == 0) ? __ldg(&x[g0 * 2]) : zA[tk];
            float zkeep = (ps == 0) ? zy : zx;
            float ix = zx * 63.f, iy = zy * 63.f;
            float ix0 = floorf(ix), iy0 = floorf(iy);
            float wx1 = ix - ix0, wx0 = 1.f - wx1;
            float wy1 = iy - iy0, wy0 = 1.f - wy1;
            float acc[32];
#pragma unroll
            for (int i = 0; i < 32; i++) acc[i] = 0.f;
            float cxs[4] = {ix0, ix0 + 1.f, ix0, ix0 + 1.f};
            float cys[4] = {iy0, iy0, iy0 + 1.f, iy0 + 1.f};
            float cws[4] = {wy0 * wx0, wy0 * wx1, wy1 * wx0, wy1 * wx1};
#pragma unroll
            for (int cr = 0; cr < 4; cr++) {
                float xf = cxs[cr], yf = cys[cr], wt = cws[cr];
                if (xf >= 0.f && xf <= 63.f && yf >= 0.f && yf <= 63.f) {
                    int xi = (int)xf, yi = (int)yf;
                    const __half2* src = (const __half2*)(
                        g_wT + ((((size_t)((b << 6) | yi) << 6 | xi)) << 6) + (p << 5));
#pragma unroll
                    for (int j = 0; j < 16; j++) {
                        float2 f = __half22float2(src[j]);
                        acc[2 * j]     += wt * f.x;
                        acc[2 * j + 1] += wt * f.y;
                    }
                }
            }
            __half* crow = combS + tk * SC;
            __half2* dst = (__half2*)(crow + p * 32);
#pragma unroll
            for (int j = 0; j < 16; j++) dst[j] = __floats2half2_rn(acc[2 * j], acc[2 * j + 1]);
            if (p == 0) {
#pragma unroll
                for (int i = 0; i < 16; i++)
                    crow[64 + i] = __float2half_rn(__ldg(&cond[b * 16 + i]));
                crow[80] = __float2half_rn(zkeep);
#pragma unroll
                for (int cc = 81; cc < 88; cc++) crow[cc] = __float2half_rn(0.f);
            } else {
#pragma unroll
                for (int cc = 88; cc < 96; cc++) crow[cc] = __float2half_rn(0.f);
            }
        }
        __syncthreads();   // comb visible

        // ===== 8 layers of this pass =====
        for (int l = 0; l < 8; l++) {
            int li = ps * 8 + l;
            const uint4* wfB = g_wfrag + ((size_t)li << 11) + (colg << 10) + lane;
            const __half* lbH = sbiasH + li * 128 + 64 * colg;
            int hr = lastw;          // buffer to read (last written)
            int hw = lastw ^ 1;      // buffer to write

            if (l < 4) {
                // ================= s-net: fp32 accumulate =================
                float acc[2][8][4];
#pragma unroll
                for (int mt = 0; mt < 2; mt++)
#pragma unroll
                    for (int nt = 0; nt < 8; nt++)
#pragma unroll
                        for (int q = 0; q < 4; q++) acc[mt][nt][q] = 0.f;

                if (l == 0) {
                    uint32_t a0 = combA + ((32 * rowg + aRow) * SC + aK) * 2;
                    uint32_t a1 = a0 + 16 * SC * 2;
#pragma unroll
                    for (int ks = 0; ks < 6; ks++) {
                        unsigned af0[4], af1[4];
                        ldsm_x4(af0, a0 + ks * 32);
                        ldsm_x4(af1, a1 + ks * 32);
#pragma unroll
                        for (int ntp = 0; ntp < 4; ntp++) {
                            uint4 bf = __ldg(wfB + (ntp * 8 + ks) * 32);
                            mma16816(acc[0][2 * ntp],     af0[0], af0[1], af0[2], af0[3], bf.x, bf.y);
                            mma16816(acc[0][2 * ntp + 1], af0[0], af0[1], af0[2], af0[3], bf.z, bf.w);
                            mma16816(acc[1][2 * ntp],     af1[0], af1[1], af1[2], af1[3], bf.x, bf.y);
                            mma16816(acc[1][2 * ntp + 1], af1[0], af1[1], af1[2], af1[3], bf.z, bf.w);
                        }
                    }
                } else {
                    int pc = colg ^ 1;
                    uint32_t pbase = hexA[hr] + ((32 * rowg + aRow) * SHE + 64 * pc + aK) * 2;
                    int pks0 = 4 * pc, oks0 = 4 * colg;
#pragma unroll
                    for (int q = 0; q < 4; q++) {
                        unsigned af0[4], af1[4];
                        ldsm_x4(af0, pbase + q * 32);
                        ldsm_x4(af1, pbase + 16 * SHE * 2 + q * 32);
#pragma unroll
                        for (int ntp = 0; ntp < 4; ntp++) {
                            uint4 bf = __ldg(wfB + (ntp * 8 + pks0 + q) * 32);
                            mma16816(acc[0][2 * ntp],     af0[0], af0[1], af0[2], af0[3], bf.x, bf.y);
                            mma16816(acc[0][2 * ntp + 1], af0[0], af0[1], af0[2], af0[3], bf.z, bf.w);
                            mma16816(acc[1][2 * ntp],     af1[0], af1[1], af1[2], af1[3], bf.x, bf.y);
                            mma16816(acc[1][2 * ntp + 1], af1[0], af1[1], af1[2], af1[3], bf.z, bf.w);
                        }
                    }
#pragma unroll
                    for (int q = 0; q < 4; q++) {
#pragma unroll
                        for (int ntp = 0; ntp < 4; ntp++) {
                            uint4 bf = __ldg(wfB + (ntp * 8 + oks0 + q) * 32);
                            mma16816(acc[0][2 * ntp], aPack[0][2 * q][0], aPack[0][2 * q][1],
                                     aPack[0][2 * q + 1][0], aPack[0][2 * q + 1][1], bf.x, bf.y);
                            mma16816(acc[0][2 * ntp + 1], aPack[0][2 * q][0], aPack[0][2 * q][1],
                                     aPack[0][2 * q + 1][0], aPack[0][2 * q + 1][1], bf.z, bf.w);
                            mma16816(acc[1][2 * ntp], aPack[1][2 * q][0], aPack[1][2 * q][1],
                                     aPack[1][2 * q + 1][0], aPack[1][2 * q + 1][1], bf.x, bf.y);
                            mma16816(acc[1][2 * ntp + 1], aPack[1][2 * q][0], aPack[1][2 * q][1],
                                     aPack[1][2 * q + 1][0], aPack[1][2 * q + 1][1], bf.z, bf.w);
                        }
                    }
                }

                if (l == 3) {
                    const float* w2 = w2s + ps * 256 + 64 * colg;
#pragma unroll
                    for (int mt = 0; mt < 2; mt++) {
                        float p0 = 0.f, p1 = 0.f;
#pragma unroll
                        for (int nt = 0; nt < 8; nt++) {
                            int c = nt * 8 + tig * 2;
                            float2 bf2 = __half22float2(*(const __half2*)(lbH + c));
                            float w0 = w2[c], w1 = w2[c + 1];
                            p0 += fast_silu(acc[mt][nt][0] + bf2.x) * w0
                                + fast_silu(acc[mt][nt][1] + bf2.y) * w1;
                            p1 += fast_silu(acc[mt][nt][2] + bf2.x) * w0
                                + fast_silu(acc[mt][nt][3] + bf2.y) * w1;
                        }
                        p0 += __shfl_xor_sync(0xffffffffu, p0, 1);
                        p0 += __shfl_xor_sync(0xffffffffu, p0, 2);
                        p1 += __shfl_xor_sync(0xffffffffu, p1, 1);
                        p1 += __shfl_xor_sync(0xffffffffu, p1, 2);
                        if (tig == 0) {
                            spartS[colg * 128 + 32 * rowg + 16 * mt + gid]     = p0;
                            spartS[colg * 128 + 32 * rowg + 16 * mt + gid + 8] = p1;
                        }
                    }
                } else {
#pragma unroll
                    for (int mt = 0; mt < 2; mt++) {
                        __half* exb = hexP[hw] + (32 * rowg + 16 * mt + gid) * SHE + 64 * colg + tig * 2;
#pragma unroll
                        for (int nt = 0; nt < 8; nt++) {
                            float2 bf2 = __half22float2(*(const __half2*)(lbH + nt * 8 + tig * 2));
                            unsigned r0 = packh2(fast_silu(acc[mt][nt][0] + bf2.x),
                                                 fast_silu(acc[mt][nt][1] + bf2.y));
                            unsigned r1 = packh2(fast_silu(acc[mt][nt][2] + bf2.x),
                                                 fast_silu(acc[mt][nt][3] + bf2.y));
                            aPack[mt][nt][0] = r0;
                            aPack[mt][nt][1] = r1;
                            *(unsigned*)(exb + nt * 8)           = r0;
                            *(unsigned*)(exb + 8 * SHE + nt * 8) = r1;
                        }
                    }
                    lastw = hw;
                }
            } else {
                // ================= t-net: fp16 accumulate =================
                unsigned acch[2][8][2];
#pragma unroll
                for (int mt = 0; mt < 2; mt++)
#pragma unroll
                    for (int nt = 0; nt < 8; nt++) { acch[mt][nt][0] = 0u; acch[mt][nt][1] = 0u; }

                if (l == 4) {
                    uint32_t a0 = combA + ((32 * rowg + aRow) * SC + aK) * 2;
                    uint32_t a1 = a0 + 16 * SC * 2;
#pragma unroll
                    for (int ks = 0; ks < 6; ks++) {
                        unsigned af0[4], af1[4];
                        ldsm_x4(af0, a0 + ks * 32);
                        ldsm_x4(af1, a1 + ks * 32);
#pragma unroll
                        for (int ntp = 0; ntp < 4; ntp++) {
                            uint4 bf = __ldg(wfB + (ntp * 8 + ks) * 32);
                            mma16816h(acch[0][2 * ntp],     af0[0], af0[1], af0[2], af0[3], bf.x, bf.y);
                            mma16816h(acch[0][2 * ntp + 1], af0[0], af0[1], af0[2], af0[3], bf.z, bf.w);
                            mma16816h(acch[1][2 * ntp],     af1[0], af1[1], af1[2], af1[3], bf.x, bf.y);
                            mma16816h(acch[1][2 * ntp + 1], af1[0], af1[1], af1[2], af1[3], bf.z, bf.w);
                        }
                    }
                } else {
                    int pc = colg ^ 1;
                    uint32_t pbase = hexA[hr] + ((32 * rowg + aRow) * SHE + 64 * pc + aK) * 2;
                    int pks0 = 4 * pc, oks0 = 4 * colg;
#pragma unroll
                    for (int q = 0; q < 4; q++) {
                        unsigned af0[4], af1[4];
                        ldsm_x4(af0, pbase + q * 32);
                        ldsm_x4(af1, pbase + 16 * SHE * 2 + q * 32);
#pragma unroll
                        for (int ntp = 0; ntp < 4; ntp++) {
                            uint4 bf = __ldg(wfB + (ntp * 8 + pks0 + q) * 32);
                            mma16816h(acch[0][2 * ntp],     af0[0], af0[1], af0[2], af0[3], bf.x, bf.y);
                            mma16816h(acch[0][2 * ntp + 1], af0[0], af0[1], af0[2], af0[3], bf.z, bf.w);
                            mma16816h(acch[1][2 * ntp],     af1[0], af1[1], af1[2], af1[3], bf.x, bf.y);
                            mma16816h(acch[1][2 * ntp + 1], af1[0], af1[1], af1[2], af1[3], bf.z, bf.w);
                        }
                    }
#pragma unroll
                    for (int q = 0; q < 4; q++) {
#pragma unroll
                        for (int ntp = 0; ntp < 4; ntp++) {
                            uint4 bf = __ldg(wfB + (ntp * 8 + oks0 + q) * 32);
                            mma16816h(acch[0][2 * ntp], aPack[0][2 * q][0], aPack[0][2 * q][1],
                                      aPack[0][2 * q + 1][0], aPack[0][2 * q + 1][1], bf.x, bf.y);
                            mma16816h(acch[0][2 * ntp + 1], aPack[0][2 * q][0], aPack[0][2 * q][1],
                                      aPack[0][2 * q + 1][0], aPack[0][2 * q + 1][1], bf.z, bf.w);
                            mma16816h(acch[1][2 * ntp], aPack[1][2 * q][0], aPack[1][2 * q][1],
                                      aPack[1][2 * q + 1][0], aPack[1][2 * q + 1][1], bf.x, bf.y);
                            mma16816h(acch[1][2 * ntp + 1], aPack[1][2 * q][0], aPack[1][2 * q][1],
                                      aPack[1][2 * q + 1][0], aPack[1][2 * q + 1][1], bf.z, bf.w);
                        }
                    }
                }

                if (l == 7) {
                    const float* w2 = w2s + ps * 256 + 128 + 64 * colg;
#pragma unroll
                    for (int mt = 0; mt < 2; mt++) {
                        float p0 = 0.f, p1 = 0.f;
#pragma unroll
                        for (int nt = 0; nt < 8; nt++) {
                            int c = nt * 8 + tig * 2;
                            __half2 bias = *(const __half2*)(lbH + c);
                            float w0 = w2[c], w1 = w2[c + 1];
                            float2 f0 = __half22float2(silu_h2h(__hadd2(*(__half2*)&acch[mt][nt][0], bias)));
                            float2 f1 = __half22float2(silu_h2h(__hadd2(*(__half2*)&acch[mt][nt][1], bias)));
                            p0 += f0.x * w0 + f0.y * w1;
                            p1 += f1.x * w0 + f1.y * w1;
                        }
                        p0 += __shfl_xor_sync(0xffffffffu, p0, 1);
                        p0 += __shfl_xor_sync(0xffffffffu, p0, 2);
                        p1 += __shfl_xor_sync(0xffffffffu, p1, 1);
                        p1 += __shfl_xor_sync(0xffffffffu, p1, 2);
                        if (tig == 0) {
                            spartT[colg * 128 + 32 * rowg + 16 * mt + gid]     = p0;
                            spartT[colg * 128 + 32 * rowg + 16 * mt + gid + 8] = p1;
                        }
                    }
                } else {
#pragma unroll
                    for (int mt = 0; mt < 2; mt++) {
                        __half* exb = hexP[hw] + (32 * rowg + 16 * mt + gid) * SHE + 64 * colg + tig * 2;
#pragma unroll
                        for (int nt = 0; nt < 8; nt++) {
                            __half2 bias = *(const __half2*)(lbH + nt * 8 + tig * 2);
                            __half2 h0 = silu_h2h(__hadd2(*(__half2*)&acch[mt][nt][0], bias));
                            __half2 h1 = silu_h2h(__hadd2(*(__half2*)&acch[mt][nt][1], bias));
                            unsigned r0 = *(unsigned*)&h0;
                            unsigned r1 = *(unsigned*)&h1;
                            aPack[mt][nt][0] = r0;
                            aPack[mt][nt][1] = r1;
                            *(unsigned*)(exb + nt * 8)           = r0;
                            *(unsigned*)(exb + 8 * SHE + nt * 8) = r1;
                        }
                    }
                    lastw = hw;
                }
            }

            __syncthreads();   // hEx writes visible; prior hEx/comb reads complete
        }

        // ===== coupling epilogue for this pass =====
        if (tid < TOKPC) {
            int g0 = tile * TOKPC + tid;
            float zold = (ps == 0) ? __ldg(&x[g0 * 2]) : __ldg(&x[g0 * 2 + 1]);
            float s_lin = spartS[tid] + spartS[128 + tid] + __ldg(&b2[ps * 2]);
            float t_lin = spartT[tid] + spartT[128 + tid] + __ldg(&b2[ps * 2 + 1]);
            float sv = tanhf(s_lin) * 1.5f;
            float z = zold * __expf(sv) + t_lin;
            out[g0 * 2 + ps] = z;
            if (ps == 0) { zA[tid] = z; sred[tid] = sv; }
            else sred[tid] += sv;
        }
        __syncthreads();
    }

    // ===== deterministic block reduce of s (both passes) =====
    if (tid < 64) sred[tid] += sred[tid + 64];
    __syncthreads();
    if (tid < 32) {
        float v = sred[tid] + sred[tid + 32];
#pragma unroll
        for (int off = 16; off; off >>= 1) v += __shfl_xor_sync(0xffffffffu, v, off);
        if (tid == 0) g_part[tile] = v;
    }
}

// ---------------- log-det reduce ----------------
__global__ void k_reduce(float* __restrict__ out) {
    int b = threadIdx.x;
    if (b < BB) {
        float acc = 0.f;
        for (int i = 0; i < 32; i++)
            acc += g_part[b * 32 + i];
        out[(size_t)NTOK * 2 + b] = acc;
    }
}

// ---------------- launcher ----------------
extern "C" void kernel_launch(void* const* d_in, const int* in_sizes, int n_in,
                              void* d_out, int out_size) {
    const float* x    = (const float*)d_in[0];
    const float* w    = (const float*)d_in[1];
    const float* cond = (const float*)d_in[2];
    const float* W0   = (const float*)d_in[3];
    const float* b0   = (const float*)d_in[4];
    const float* W1   = (const float*)d_in[5];
    const float* b1   = (const float*)d_in[6];
    const float* W2   = (const float*)d_in[7];
    const float* b2   = (const float*)d_in[8];
    float* out = (float*)d_out;

    cudaFuncSetAttribute(k_fused, cudaFuncAttributeMaxDynamicSharedMemorySize, SMEM_TOT);

    k_transpose<<<4096, 256>>>(w);
    k_packfrag<<<128, 256>>>(W0, b0, W1, b1);
    k_fused<<<NCTAS, NTHREADS, SMEM_TOT>>>(x, cond, W2, b2, out);
    k_reduce<<<1, 64>>>(out);
}

// round 14
// speedup vs baseline: 1.2248x; 1.0062x over previous
#include <cuda_runtime.h>
#include <cuda_fp16.h>
#include <stdint.h>

// Problem dims
#define BB   64
#define TT   4096
#define NTOK (BB*TT)          // 262144
#define TOKPC 128             // tokens per CTA (one batch per CTA)
#define NCTAS (NTOK/TOKPC)    // 2048
#define NTHREADS 256

// smem strides (halves): row stride in 16B units coprime with 8 -> LDSM conflict-free
#define SC  72                // comb stride (K=64 + pad), 144B = 9*16B
#define SH  136               // weight stride (K=128 padded)
#define SHE 136               // hidden-exchange stride

// smem byte offsets
#define OFF_COMB   0                  // 128*SC*2  = 18432
#define OFF_HEX    18432              // 128*SHE*2 = 34816
#define OFF_WB     53248              // 128*SH*2  = 34816
#define OFF_BIAS   88064              // 2048 halves = 4096
#define OFF_W2     92160              // 512 floats  = 2048
#define OFF_C0     94208              // 256 floats  = 1024
#define OFF_W0Z    95232              // 256 floats  = 1024
#define OFF_ZK     96256              // 128 floats  = 512
#define OFF_SPS    96768              // 256 floats  = 1024
#define OFF_SPT    97792              // 256 floats  = 1024
#define OFF_ZA     98816              // 128 floats  = 512
#define OFF_SRED   99328              // 128 floats  = 512
#define SMEM_TOT   99840

// ---------------- device scratch ----------------
__device__ __align__(16) __half g_wT[(size_t)BB * 64 * 64 * 64]; // [b][y][x][c] fp16, 32MB
__device__ __align__(16) __half g_wts[4 * 4 * 128 * 128];        // [net][layer][n][k] fp16
__device__ __align__(4) __half g_biasH[4 * 4 * 128];             // [net][layer][n] fp16
__device__ float g_c0[4 * BB * 128];                             // b0 + W0_cond @ cond[b]
__device__ float g_w0z[4 * 128];                                 // W0[:, zcol]
__device__ float g_part[NCTAS];                                  // per-tile s-sums

// ---------------- helpers ----------------
__device__ __forceinline__ void mma16816(float c[4], const unsigned a0, const unsigned a1,
                                         const unsigned a2, const unsigned a3,
                                         unsigned b0, unsigned b1) {
    asm volatile(
        "mma.sync.aligned.m16n8k16.row.col.f32.f16.f16.f32 "
        "{%0,%1,%2,%3}, {%4,%5,%6,%7}, {%8,%9}, {%0,%1,%2,%3};"
        : "+f"(c[0]), "+f"(c[1]), "+f"(c[2]), "+f"(c[3])
        : "r"(a0), "r"(a1), "r"(a2), "r"(a3), "r"(b0), "r"(b1));
}

__device__ __forceinline__ void mma16816h(unsigned c[2], const unsigned a0, const unsigned a1,
                                          const unsigned a2, const unsigned a3,
                                          unsigned b0, unsigned b1) {
    asm volatile(
        "mma.sync.aligned.m16n8k16.row.col.f16.f16.f16.f16 "
        "{%0,%1}, {%2,%3,%4,%5}, {%6,%7}, {%0,%1};"
        : "+r"(c[0]), "+r"(c[1])
        : "r"(a0), "r"(a1), "r"(a2), "r"(a3), "r"(b0), "r"(b1));
}

__device__ __forceinline__ void ldsm_x4(unsigned r[4], uint32_t addr) {
    asm volatile("ldmatrix.sync.aligned.m8n8.x4.shared.b16 {%0,%1,%2,%3}, [%4];"
                 : "=r"(r[0]), "=r"(r[1]), "=r"(r[2]), "=r"(r[3]) : "r"(addr));
}

__device__ __forceinline__ uint32_t smem_u32(const void* p) {
    uint32_t a;
    asm("{ .reg .u64 t; cvta.to.shared.u64 t, %1; cvt.u32.u64 %0, t; }" : "=r"(a) : "l"(p));
    return a;
}

__device__ __forceinline__ float fast_silu(float v) {
    float t;
    asm("tanh.approx.f32 %0, %1;" : "=f"(t) : "f"(0.5f * v));
    return 0.5f * v * (t + 1.0f);
}
__device__ __forceinline__ unsigned packh2(float a, float b) {
    __half2 h = __floats2half2_rn(a, b);
    return *(unsigned*)&h;
}
__device__ __forceinline__ __half2 silu_h2h(__half2 p) {
    __half2 u = __hmul2(p, __float2half2_rn(0.5f));
    __half2 t;
    asm("tanh.approx.f16x2 %0, %1;" : "=r"(*(unsigned*)&t) : "r"(*(unsigned*)&u));
    return __hfma2(u, t, u);
}

#define CP_ASYNC16(dst, src) \
    asm volatile("cp.async.cg.shared.global [%0], [%1], 16;" :: "r"(dst), "l"(src))
#define CP_COMMIT() asm volatile("cp.async.commit_group;" ::: "memory")
#define CP_WAIT0()  asm volatile("cp.async.wait_group 0;" ::: "memory")

// ---------------- transpose w[B,C,H,W] f32 -> wT[b][y][x][c] fp16 ----------------
__global__ void k_transpose(const float* __restrict__ w) {
    __shared__ float tile[64][65];
    int bid = blockIdx.x;
    int b = bid >> 6, y = bid & 63;
    int t = threadIdx.x;
    {
        int c = t >> 2, xq = (t & 3) * 16;
        const float4* src = (const float4*)(w + ((((b << 6) | c) << 6 | y) << 6) + xq);
#pragma unroll
        for (int j = 0; j < 4; j++) {
            float4 v = src[j];
            tile[c][xq + 4 * j + 0] = v.x;
            tile[c][xq + 4 * j + 1] = v.y;
            tile[c][xq + 4 * j + 2] = v.z;
            tile[c][xq + 4 * j + 3] = v.w;
        }
    }
    __syncthreads();
    {
        int xx = t >> 2, cq = (t & 3) * 16;
        __half2* dst = (__half2*)(g_wT + ((((size_t)(((b << 6) | y)) << 6 | xx)) << 6) + cq);
#pragma unroll
        for (int j = 0; j < 8; j++)
            dst[j] = __floats2half2_rn(tile[cq + 2 * j][xx], tile[cq + 2 * j + 1][xx]);
    }
}

// ---------------- pack weights + precompute c0/w0z ----------------
// g_wts permuted cols: [lf 0..63 | (unused cond/z cols zeroed) ]; layer0 only reads k<64.
__global__ void k_pack(const float* __restrict__ W0, const float* __restrict__ b0,
                       const float* __restrict__ W1, const float* __restrict__ b1,
                       const float* __restrict__ cond) {
    int idx = blockIdx.x * 256 + threadIdx.x;      // 262144 total
    int net = idx >> 16;
    int rem = idx & 65535;
    int layer = rem >> 14;
    int rem2 = rem & 16383;
    int n = rem2 >> 7, k = rem2 & 127;
    float v = 0.f;
    if (layer == 0) {
        if (k < 64) v = W0[(net * 128 + n) * 81 + 1 + k];   // lf cols only
    } else {
        v = W1[((net * 3 + (layer - 1)) * 128 + n) * 128 + k];
    }
    g_wts[idx] = __float2half_rn(v);
    if (idx < 2048) {
        int bn = idx >> 9, bl = (idx >> 7) & 3, bb_ = idx & 127;
        float bv = (bl == 0) ? b0[bn * 128 + bb_]
                             : b1[((bn * 3 + bl - 1) * 128) + bb_];
        g_biasH[idx] = __float2half_rn(bv);
    }
    // c0[net][b][n] = b0[net][n] + sum_j W0[net][n][65+j] * cond[b][j]
    if (idx < 4 * BB * 128) {
        int cn = idx >> 13;            // net
        int cb = (idx >> 7) & 63;      // batch
        int cn2 = idx & 127;           // n
        float acc = b0[cn * 128 + cn2];
        const float* wr = W0 + (cn * 128 + cn2) * 81 + 65;
        const float* cr = cond + cb * 16;
#pragma unroll
        for (int j = 0; j < 16; j++) acc += wr[j] * cr[j];
        g_c0[idx] = acc;
    }
    if (idx < 512) {
        int zn = idx >> 7, zn2 = idx & 127;
        g_w0z[idx] = W0[(zn * 128 + zn2) * 81 + 0];
    }
}

// ---------------- fused two-pass coupling kernel ----------------
__global__ void __launch_bounds__(NTHREADS, 2) k_fused(
    const float* __restrict__ x, const float* __restrict__ cond,
    const float* __restrict__ W2, const float* __restrict__ b2,
    float* __restrict__ out) {
    extern __shared__ __align__(16) char smraw[];
    __half* combS  = (__half*)(smraw + OFF_COMB);
    __half* hExS   = (__half*)(smraw + OFF_HEX);
    __half* sbiasH = (__half*)(smraw + OFF_BIAS);
    float*  w2s    = (float*)(smraw + OFF_W2);
    float*  c0s    = (float*)(smraw + OFF_C0);    // [2][128] this pass's nets
    float*  w0zs   = (float*)(smraw + OFF_W0Z);   // [2][128]
    float*  zK     = (float*)(smraw + OFF_ZK);    // per-token z_keep
    float*  spartS = (float*)(smraw + OFF_SPS);
    float*  spartT = (float*)(smraw + OFF_SPT);
    float*  zA     = (float*)(smraw + OFF_ZA);
    float*  sred   = (float*)(smraw + OFF_SRED);

    int tid = threadIdx.x;
    int wid = tid >> 5, lane = tid & 31;
    int gid = lane >> 2, tig = lane & 3;
    int rowg = wid & 3;          // 4 row-groups x 32 tokens = 128
    int colg = wid >> 2;         // 2 col-groups x 64 cols
    int tile = blockIdx.x;
    int batch = tile >> 5;       // whole CTA in one batch

    uint32_t combA = smem_u32(combS);
    uint32_t hExA  = smem_u32(hExS);
    uint32_t wbA   = smem_u32(smraw + OFF_WB);

    // prefetch layer 0 weights
#pragma unroll
    for (int i = 0; i < 8; i++) {
        int ci = tid + i * 256;
        int n = ci >> 4, q = ci & 15;
        CP_ASYNC16(wbA + (n * SH + q * 8) * 2, (const char*)g_wts + ci * 16);
    }
    CP_COMMIT();

    // stage biases (all 16 layers) + w2 (all 4 nets)
#pragma unroll
    for (int i = 0; i < 4; i++)
        ((unsigned*)sbiasH)[tid + i * 256] = ((const unsigned*)g_biasH)[tid + i * 256];
    w2s[tid] = __ldg(&W2[tid]);
    w2s[tid + 256] = __ldg(&W2[tid + 256]);

    // ldmatrix per-thread offsets
    int aRow = lane & 15;
    int aK   = (lane >> 4) * 8;
    int bRow = (lane & 7) + ((lane >> 4) & 1) * 8;
    int bK   = ((lane >> 3) & 1) * 8;

    unsigned aPack[2][8][2];

    for (int ps = 0; ps < 2; ps++) {
        // stage c0 / w0z for this pass's 2 nets
        {
            int jn = tid >> 7, jj = tid & 127;   // tid<256 covers [2][128]
            int net = ps * 2 + jn;
            c0s[tid]  = g_c0[(net * BB + batch) * 128 + jj];
            w0zs[tid] = g_w0z[net * 128 + jj];
        }

        // ===== gather + build comb (2 threads per token, vectorized LDG.128) =====
        {
            int tk = tid >> 1, p = tid & 1;
            int g0 = tile * TOKPC + tk;
            int b = g0 >> 12;
            float zy = __ldg(&x[g0 * 2 + 1]);
            float zx = (ps == 0) ? __ldg(&x[g0 * 2]) : zA[tk];
            float zkeep = (ps == 0) ? zy : zx;
            float ix = zx * 63.f, iy = zy * 63.f;
            float ix0 = floorf(ix), iy0 = floorf(iy);
            float wx1 = ix - ix0, wx0 = 1.f - wx1;
            float wy1 = iy - iy0, wy0 = 1.f - wy1;
            float acc[32];
#pragma unroll
            for (int i = 0; i < 32; i++) acc[i] = 0.f;
            float cxs[4] = {ix0, ix0 + 1.f, ix0, ix0 + 1.f};
            float cys[4] = {iy0, iy0, iy0 + 1.f, iy0 + 1.f};
            float cws[4] = {wy0 * wx0, wy0 * wx1, wy1 * wx0, wy1 * wx1};
#pragma unroll
            for (int cr = 0; cr < 4; cr++) {
                float xf = cxs[cr], yf = cys[cr], wt = cws[cr];
                if (xf >= 0.f && xf <= 63.f && yf >= 0.f && yf <= 63.f) {
                    int xi = (int)xf, yi = (int)yf;
                    const uint4* src = (const uint4*)((const char*)g_wT +
                        (((size_t)(((b << 6) | yi) << 6 | xi)) << 7) + (p << 6));
#pragma unroll
                    for (int u = 0; u < 4; u++) {
                        uint4 v = __ldg(src + u);
                        unsigned ww[4] = {v.x, v.y, v.z, v.w};
#pragma unroll
                        for (int q = 0; q < 4; q++) {
                            float2 f = __half22float2(*(__half2*)&ww[q]);
                            acc[u * 8 + 2 * q]     += wt * f.x;
                            acc[u * 8 + 2 * q + 1] += wt * f.y;
                        }
                    }
                }
            }
            uint4* dst = (uint4*)((char*)combS + tk * (SC * 2) + p * 64);
#pragma unroll
            for (int u = 0; u < 4; u++) {
                uint4 o;
                o.x = packh2(acc[u * 8 + 0], acc[u * 8 + 1]);
                o.y = packh2(acc[u * 8 + 2], acc[u * 8 + 3]);
                o.z = packh2(acc[u * 8 + 4], acc[u * 8 + 5]);
                o.w = packh2(acc[u * 8 + 6], acc[u * 8 + 7]);
                dst[u] = o;
            }
            if (p == 0) zK[tk] = zkeep;
        }
        CP_WAIT0();
        __syncthreads();   // comb + zK + c0s + weights visible

        // ===== 8 layers of this pass =====
        for (int l = 0; l < 8; l++) {
            int li = ps * 8 + l;
            uint32_t bb = wbA + ((64 * colg + bRow) * SH + bK) * 2;
            const __half* lbH = sbiasH + li * 128 + 64 * colg;
            const float* c0p  = c0s + (l >> 2) * 128 + 64 * colg;
            const float* w0zp = w0zs + (l >> 2) * 128 + 64 * colg;

            if (l < 4) {
                // ================= s-net: fp32 accumulate =================
                float acc[2][8][4];
#pragma unroll
                for (int mt = 0; mt < 2; mt++)
#pragma unroll
                    for (int nt = 0; nt < 8; nt++)
#pragma unroll
                        for (int q = 0; q < 4; q++) acc[mt][nt][q] = 0.f;

                if (l == 0) {
                    uint32_t a0 = combA + ((32 * rowg + aRow) * SC + aK) * 2;
                    uint32_t a1 = a0 + 16 * SC * 2;
#pragma unroll
                    for (int ks = 0; ks < 4; ks++) {
                        unsigned af0[4], af1[4];
                        ldsm_x4(af0, a0 + ks * 32);
                        ldsm_x4(af1, a1 + ks * 32);
#pragma unroll
                        for (int ntp = 0; ntp < 4; ntp++) {
                            unsigned bf[4];
                            ldsm_x4(bf, bb + (ntp * 16 * SH) * 2 + ks * 32);
                            mma16816(acc[0][2 * ntp],     af0[0], af0[1], af0[2], af0[3], bf[0], bf[1]);
                            mma16816(acc[0][2 * ntp + 1], af0[0], af0[1], af0[2], af0[3], bf[2], bf[3]);
                            mma16816(acc[1][2 * ntp],     af1[0], af1[1], af1[2], af1[3], bf[0], bf[1]);
                            mma16816(acc[1][2 * ntp + 1], af1[0], af1[1], af1[2], af1[3], bf[2], bf[3]);
                        }
                    }
                } else {
                    int pc = colg ^ 1;
                    uint32_t pbase = hExA + ((32 * rowg + aRow) * SHE + 64 * pc + aK) * 2;
                    int pks0 = 4 * pc, oks0 = 4 * colg;
#pragma unroll
                    for (int q = 0; q < 4; q++) {
                        unsigned af0[4], af1[4];
                        ldsm_x4(af0, pbase + q * 32);
                        ldsm_x4(af1, pbase + 16 * SHE * 2 + q * 32);
#pragma unroll
                        for (int ntp = 0; ntp < 4; ntp++) {
                            unsigned bf[4];
                            ldsm_x4(bf, bb + (ntp * 16 * SH) * 2 + (pks0 + q) * 32);
                            mma16816(acc[0][2 * ntp],     af0[0], af0[1], af0[2], af0[3], bf[0], bf[1]);
                            mma16816(acc[0][2 * ntp + 1], af0[0], af0[1], af0[2], af0[3], bf[2], bf[3]);
                            mma16816(acc[1][2 * ntp],     af1[0], af1[1], af1[2], af1[3], bf[0], bf[1]);
                            mma16816(acc[1][2 * ntp + 1], af1[0], af1[1], af1[2], af1[3], bf[2], bf[3]);
                        }
                    }
#pragma unroll
                    for (int q = 0; q < 4; q++) {
#pragma unroll
                        for (int ntp = 0; ntp < 4; ntp++) {
                            unsigned bf[4];
                            ldsm_x4(bf, bb + (ntp * 16 * SH) * 2 + (oks0 + q) * 32);
                            mma16816(acc[0][2 * ntp], aPack[0][2 * q][0], aPack[0][2 * q][1],
                                     aPack[0][2 * q + 1][0], aPack[0][2 * q + 1][1], bf[0], bf[1]);
                            mma16816(acc[0][2 * ntp + 1], aPack[0][2 * q][0], aPack[0][2 * q][1],
                                     aPack[0][2 * q + 1][0], aPack[0][2 * q + 1][1], bf[2], bf[3]);
                            mma16816(acc[1][2 * ntp], aPack[1][2 * q][0], aPack[1][2 * q][1],
                                     aPack[1][2 * q + 1][0], aPack[1][2 * q + 1][1], bf[0], bf[1]);
                            mma16816(acc[1][2 * ntp + 1], aPack[1][2 * q][0], aPack[1][2 * q][1],
                                     aPack[1][2 * q + 1][0], aPack[1][2 * q + 1][1], bf[2], bf[3]);
                        }
                    }
                }

                __syncthreads();   // all MMA reads done

                if (li < 15) {
                    const char* srcp = (const char*)g_wts + ((size_t)(li + 1) << 15);
#pragma unroll
                    for (int i = 0; i < 8; i++) {
                        int ci = tid + i * 256;
                        int n = ci >> 4, q = ci & 15;
                        CP_ASYNC16(wbA + (n * SH + q * 8) * 2, srcp + ci * 16);
                    }
                    CP_COMMIT();
                }

                if (l == 3) {
                    const float* w2 = w2s + ps * 256 + 64 * colg;
#pragma unroll
                    for (int mt = 0; mt < 2; mt++) {
                        float p0 = 0.f, p1 = 0.f;
#pragma unroll
                        for (int nt = 0; nt < 8; nt++) {
                            int c = nt * 8 + tig * 2;
                            float2 bf2 = __half22float2(*(const __half2*)(lbH + c));
                            float w0 = w2[c], w1 = w2[c + 1];
                            p0 += fast_silu(acc[mt][nt][0] + bf2.x) * w0
                                + fast_silu(acc[mt][nt][1] + bf2.y) * w1;
                            p1 += fast_silu(acc[mt][nt][2] + bf2.x) * w0
                                + fast_silu(acc[mt][nt][3] + bf2.y) * w1;
                        }
                        p0 += __shfl_xor_sync(0xffffffffu, p0, 1);
                        p0 += __shfl_xor_sync(0xffffffffu, p0, 2);
                        p1 += __shfl_xor_sync(0xffffffffu, p1, 1);
                        p1 += __shfl_xor_sync(0xffffffffu, p1, 2);
                        if (tig == 0) {
                            spartS[colg * 128 + 32 * rowg + 16 * mt + gid]     = p0;
                            spartS[colg * 128 + 32 * rowg + 16 * mt + gid + 8] = p1;
                        }
                    }
                } else {
#pragma unroll
                    for (int mt = 0; mt < 2; mt++) {
                        int r = 32 * rowg + 16 * mt + gid;
                        float z0 = (l == 0) ? zK[r] : 0.f;
                        float z1 = (l == 0) ? zK[r + 8] : 0.f;
                        __half* exb = hExS + r * SHE + 64 * colg + tig * 2;
#pragma unroll
                        for (int nt = 0; nt < 8; nt++) {
                            int c = nt * 8 + tig * 2;
                            float b00, b01, b10, b11;
                            if (l == 0) {
                                float cc0 = c0p[c], cc1 = c0p[c + 1];
                                float wz0 = w0zp[c], wz1 = w0zp[c + 1];
                                b00 = cc0 + z0 * wz0; b01 = cc1 + z0 * wz1;
                                b10 = cc0 + z1 * wz0; b11 = cc1 + z1 * wz1;
                            } else {
                                float2 bf2 = __half22float2(*(const __half2*)(lbH + c));
                                b00 = bf2.x; b01 = bf2.y; b10 = bf2.x; b11 = bf2.y;
                            }
                            unsigned r0 = packh2(fast_silu(acc[mt][nt][0] + b00),
                                                 fast_silu(acc[mt][nt][1] + b01));
                            unsigned r1 = packh2(fast_silu(acc[mt][nt][2] + b10),
                                                 fast_silu(acc[mt][nt][3] + b11));
                            aPack[mt][nt][0] = r0;
                            aPack[mt][nt][1] = r1;
                            *(unsigned*)(exb + nt * 8)           = r0;
                            *(unsigned*)(exb + 8 * SHE + nt * 8) = r1;
                        }
                    }
                }
            } else {
                // ================= t-net: fp16 accumulate =================
                unsigned acch[2][8][2];
#pragma unroll
                for (int mt = 0; mt < 2; mt++)
#pragma unroll
                    for (int nt = 0; nt < 8; nt++) { acch[mt][nt][0] = 0u; acch[mt][nt][1] = 0u; }

                if (l == 4) {
                    uint32_t a0 = combA + ((32 * rowg + aRow) * SC + aK) * 2;
                    uint32_t a1 = a0 + 16 * SC * 2;
#pragma unroll
                    for (int ks = 0; ks < 4; ks++) {
                        unsigned af0[4], af1[4];
                        ldsm_x4(af0, a0 + ks * 32);
                        ldsm_x4(af1, a1 + ks * 32);
#pragma unroll
                        for (int ntp = 0; ntp < 4; ntp++) {
                            unsigned bf[4];
                            ldsm_x4(bf, bb + (ntp * 16 * SH) * 2 + ks * 32);
                            mma16816h(acch[0][2 * ntp],     af0[0], af0[1], af0[2], af0[3], bf[0], bf[1]);
                            mma16816h(acch[0][2 * ntp + 1], af0[0], af0[1], af0[2], af0[3], bf[2], bf[3]);
                            mma16816h(acch[1][2 * ntp],     af1[0], af1[1], af1[2], af1[3], bf[0], bf[1]);
                            mma16816h(acch[1][2 * ntp + 1], af1[0], af1[1], af1[2], af1[3], bf[2], bf[3]);
                        }
                    }
                } else {
                    int pc = colg ^ 1;
                    uint32_t pbase = hExA + ((32 * rowg + aRow) * SHE + 64 * pc + aK) * 2;
                    int pks0 = 4 * pc, oks0 = 4 * colg;
#pragma unroll
                    for (int q = 0; q < 4; q++) {
                        unsigned af0[4], af1[4];
                        ldsm_x4(af0, pbase + q * 32);
                        ldsm_x4(af1, pbase + 16 * SHE * 2 + q * 32);
#pragma unroll
                        for (int ntp = 0; ntp < 4; ntp++) {
                            unsigned bf[4];
                            ldsm_x4(bf, bb + (ntp * 16 * SH) * 2 + (pks0 + q) * 32);
                            mma16816h(acch[0][2 * ntp],     af0[0], af0[1], af0[2], af0[3], bf[0], bf[1]);
                            mma16816h(acch[0][2 * ntp + 1], af0[0], af0[1], af0[2], af0[3], bf[2], bf[3]);
                            mma16816h(acch[1][2 * ntp],     af1[0], af1[1], af1[2], af1[3], bf[0], bf[1]);
                            mma16816h(acch[1][2 * ntp + 1], af1[0], af1[1], af1[2], af1[3], bf[2], bf[3]);
                        }
                    }
#pragma unroll
                    for (int q = 0; q < 4; q++) {
#pragma unroll
                        for (int ntp = 0; ntp < 4; ntp++) {
                            unsigned bf[4];
                            ldsm_x4(bf, bb + (ntp * 16 * SH) * 2 + (oks0 + q) * 32);
                            mma16816h(acch[0][2 * ntp], aPack[0][2 * q][0], aPack[0][2 * q][1],
                                      aPack[0][2 * q + 1][0], aPack[0][2 * q + 1][1], bf[0], bf[1]);
                            mma16816h(acch[0][2 * ntp + 1], aPack[0][2 * q][0], aPack[0][2 * q][1],
                                      aPack[0][2 * q + 1][0], aPack[0][2 * q + 1][1], bf[2], bf[3]);
                            mma16816h(acch[1][2 * ntp], aPack[1][2 * q][0], aPack[1][2 * q][1],
                                      aPack[1][2 * q + 1][0], aPack[1][2 * q + 1][1], bf[0], bf[1]);
                            mma16816h(acch[1][2 * ntp + 1], aPack[1][2 * q][0], aPack[1][2 * q][1],
                                      aPack[1][2 * q + 1][0], aPack[1][2 * q + 1][1], bf[2], bf[3]);
                        }
                    }
                }

                __syncthreads();   // all MMA reads done

                if (li < 15) {
                    const char* srcp = (const char*)g_wts + ((size_t)(li + 1) << 15);
#pragma unroll
                    for (int i = 0; i < 8; i++) {
                        int ci = tid + i * 256;
                        int n = ci >> 4, q = ci & 15;
                        CP_ASYNC16(wbA + (n * SH + q * 8) * 2, srcp + ci * 16);
                    }
                    CP_COMMIT();
                }

                if (l == 7) {
                    const float* w2 = w2s + ps * 256 + 128 + 64 * colg;
#pragma unroll
                    for (int mt = 0; mt < 2; mt++) {
                        float p0 = 0.f, p1 = 0.f;
#pragma unroll
                        for (int nt = 0; nt < 8; nt++) {
                            int c = nt * 8 + tig * 2;
                            __half2 bias = *(const __half2*)(lbH + c);
                            float w0 = w2[c], w1 = w2[c + 1];
                            float2 f0 = __half22float2(silu_h2h(__hadd2(*(__half2*)&acch[mt][nt][0], bias)));
                            float2 f1 = __half22float2(silu_h2h(__hadd2(*(__half2*)&acch[mt][nt][1], bias)));
                            p0 += f0.x * w0 + f0.y * w1;
                            p1 += f1.x * w0 + f1.y * w1;
                        }
                        p0 += __shfl_xor_sync(0xffffffffu, p0, 1);
                        p0 += __shfl_xor_sync(0xffffffffu, p0, 2);
                        p1 += __shfl_xor_sync(0xffffffffu, p1, 1);
                        p1 += __shfl_xor_sync(0xffffffffu, p1, 2);
                        if (tig == 0) {
                            spartT[colg * 128 + 32 * rowg + 16 * mt + gid]     = p0;
                            spartT[colg * 128 + 32 * rowg + 16 * mt + gid + 8] = p1;
                        }
                    }
                } else {
#pragma unroll
                    for (int mt = 0; mt < 2; mt++) {
                        int r = 32 * rowg + 16 * mt + gid;
                        float z0 = (l == 4) ? zK[r] : 0.f;
                        float z1 = (l == 4) ? zK[r + 8] : 0.f;
                        __half* exb = hExS + r * SHE + 64 * colg + tig * 2;
#pragma unroll
                        for (int nt = 0; nt < 8; nt++) {
                            int c = nt * 8 + tig * 2;
                            __half2 bias0, bias1;
                            if (l == 4) {
                                float cc0 = c0p[c], cc1 = c0p[c + 1];
                                float wz0 = w0zp[c], wz1 = w0zp[c + 1];
                                unsigned u0 = packh2(cc0 + z0 * wz0, cc1 + z0 * wz1);
                                unsigned u1 = packh2(cc0 + z1 * wz0, cc1 + z1 * wz1);
                                bias0 = *(__half2*)&u0;
                                bias1 = *(__half2*)&u1;
                            } else {
                                bias0 = *(const __half2*)(lbH + c);
                                bias1 = bias0;
                            }
                            __half2 h0 = silu_h2h(__hadd2(*(__half2*)&acch[mt][nt][0], bias0));
                            __half2 h1 = silu_h2h(__hadd2(*(__half2*)&acch[mt][nt][1], bias1));
                            unsigned r0 = *(unsigned*)&h0;
                            unsigned r1 = *(unsigned*)&h1;
                            aPack[mt][nt][0] = r0;
                            aPack[mt][nt][1] = r1;
                            *(unsigned*)(exb + nt * 8)           = r0;
                            *(unsigned*)(exb + 8 * SHE + nt * 8) = r1;
                        }
                    }
                }
            }

            CP_WAIT0();
            __syncthreads();   // next weights ready + hEx writes visible
        }

        // ===== coupling epilogue for this pass =====
        if (tid < TOKPC) {
            int g0 = tile * TOKPC + tid;
            float zold = (ps == 0) ? __ldg(&x[g0 * 2]) : __ldg(&x[g0 * 2 + 1]);
            float s_lin = spartS[tid] + spartS[128 + tid] + __ldg(&b2[ps * 2]);
            float t_lin = spartT[tid] + spartT[128 + tid] + __ldg(&b2[ps * 2 + 1]);
            float sv = tanhf(s_lin) * 1.5f;
            float z = zold * __expf(sv) + t_lin;
            out[g0 * 2 + ps] = z;
            if (ps == 0) { zA[tid] = z; sred[tid] = sv; }
            else sred[tid] += sv;
        }
        __syncthreads();
    }

    // ===== deterministic block reduce of s (both passes) =====
    if (tid < 64) sred[tid] += sred[tid + 64];
    __syncthreads();
    if (tid < 32) {
        float v = sred[tid] + sred[tid + 32];
#pragma unroll
        for (int off = 16; off; off >>= 1) v += __shfl_xor_sync(0xffffffffu, v, off);
        if (tid == 0) g_part[tile] = v;
    }
}

// ---------------- log-det reduce ----------------
__global__ void k_reduce(float* __restrict__ out) {
    int b = threadIdx.x;
    if (b < BB) {
        float acc = 0.f;
        for (int i = 0; i < 32; i++)
            acc += g_part[b * 32 + i];
        out[(size_t)NTOK * 2 + b] = acc;
    }
}

// ---------------- launcher ----------------
extern "C" void kernel_launch(void* const* d_in, const int* in_sizes, int n_in,
                              void* d_out, int out_size) {
    const float* x    = (const float*)d_in[0];
    const float* w    = (const float*)d_in[1];
    const float* cond = (const float*)d_in[2];
    const float* W0   = (const float*)d_in[3];
    const float* b0   = (const float*)d_in[4];
    const float* W1   = (const float*)d_in[5];
    const float* b1   = (const float*)d_in[6];
    const float* W2   = (const float*)d_in[7];
    const float* b2   = (const float*)d_in[8];
    float* out = (float*)d_out;

    cudaFuncSetAttribute(k_fused, cudaFuncAttributeMaxDynamicSharedMemorySize, SMEM_TOT);

    k_transpose<<<4096, 256>>>(w);
    k_pack<<<1024, 256>>>(W0, b0, W1, b1, cond);
    k_fused<<<NCTAS, NTHREADS, SMEM_TOT>>>(x, cond, W2, b2, out);
    k_reduce<<<1, 64>>>(out);
}

// round 15
// speedup vs baseline: 1.3277x; 1.0840x over previous
#include <cuda_runtime.h>
#include <cuda_fp16.h>
#include <stdint.h>

// Problem dims
#define BB   64
#define TT   4096
#define NTOK (BB*TT)          // 262144
#define TOKPC 128             // tokens per CTA
#define NCTAS (NTOK/TOKPC)    // 2048
#define NTHREADS 256

// smem strides (halves): row stride in 16B units coprime with 8 -> LDSM/STSM conflict-free
#define SC  104               // comb stride (K=96 padded)
#define SHE 136               // hidden-exchange stride

// smem byte offsets
#define OFF_COMB   0                  // 128*SC*2  = 26624
#define OFF_HEX0   26624              // 128*SHE*2 = 34816
#define OFF_HEX1   61440              // 34816
#define OFF_BIAS   96256              // 2048 halves = 4096
#define OFF_W2     100352             // 512 floats  = 2048
#define OFF_SPS    102400             // 256 floats  = 1024
#define OFF_SPT    103424             // 256 floats  = 1024
#define OFF_ZA     104448             // 128 floats  = 512
#define OFF_SRED   104960             // 128 floats  = 512
#define SMEM_TOT   105472

// ---------------- device scratch ----------------
__device__ __align__(16) __half g_wT[(size_t)BB * 64 * 64 * 64]; // [b][y][x][c] fp16, 32MB
__device__ __align__(16) uint4 g_wfrag[16 * 2048];               // [li][colg][ntp][ks][lane] frag words
__device__ __align__(4) __half g_biasH[4 * 4 * 128];             // [net][layer][n] fp16
__device__ float g_part[NCTAS];                                  // per-tile s-sums

// ---------------- helpers ----------------
__device__ __forceinline__ void mma16816(float c[4], const unsigned a0, const unsigned a1,
                                         const unsigned a2, const unsigned a3,
                                         unsigned b0, unsigned b1) {
    asm volatile(
        "mma.sync.aligned.m16n8k16.row.col.f32.f16.f16.f32 "
        "{%0,%1,%2,%3}, {%4,%5,%6,%7}, {%8,%9}, {%0,%1,%2,%3};"
        : "+f"(c[0]), "+f"(c[1]), "+f"(c[2]), "+f"(c[3])
        : "r"(a0), "r"(a1), "r"(a2), "r"(a3), "r"(b0), "r"(b1));
}

__device__ __forceinline__ void mma16816h(unsigned c[2], const unsigned a0, const unsigned a1,
                                          const unsigned a2, const unsigned a3,
                                          unsigned b0, unsigned b1) {
    asm volatile(
        "mma.sync.aligned.m16n8k16.row.col.f16.f16.f16.f16 "
        "{%0,%1}, {%2,%3,%4,%5}, {%6,%7}, {%0,%1};"
        : "+r"(c[0]), "+r"(c[1])
        : "r"(a0), "r"(a1), "r"(a2), "r"(a3), "r"(b0), "r"(b1));
}

__device__ __forceinline__ void ldsm_x4(unsigned r[4], uint32_t addr) {
    asm volatile("ldmatrix.sync.aligned.m8n8.x4.shared.b16 {%0,%1,%2,%3}, [%4];"
                 : "=r"(r[0]), "=r"(r[1]), "=r"(r[2]), "=r"(r[3]) : "r"(addr));
}

__device__ __forceinline__ void stsm_x4(uint32_t addr, unsigned r0, unsigned r1,
                                        unsigned r2, unsigned r3) {
    asm volatile("stmatrix.sync.aligned.m8n8.x4.shared.b16 [%0], {%1,%2,%3,%4};"
                 :: "r"(addr), "r"(r0), "r"(r1), "r"(r2), "r"(r3) : "memory");
}

__device__ __forceinline__ uint32_t smem_u32(const void* p) {
    uint32_t a;
    asm("{ .reg .u64 t; cvta.to.shared.u64 t, %1; cvt.u32.u64 %0, t; }" : "=r"(a) : "l"(p));
    return a;
}

__device__ __forceinline__ float fast_silu(float v) {
    float t;
    asm("tanh.approx.f32 %0, %1;" : "=f"(t) : "f"(0.5f * v));
    return 0.5f * v * (t + 1.0f);
}
__device__ __forceinline__ unsigned packh2(float a, float b) {
    __half2 h = __floats2half2_rn(a, b);
    return *(unsigned*)&h;
}
__device__ __forceinline__ __half2 silu_h2h(__half2 p) {
    __half2 u = __hmul2(p, __float2half2_rn(0.5f));
    __half2 t;
    asm("tanh.approx.f16x2 %0, %1;" : "=r"(*(unsigned*)&t) : "r"(*(unsigned*)&u));
    return __hfma2(u, t, u);
}

// ---------------- transpose w[B,C,H,W] f32 -> wT[b][y][x][c] fp16 ----------------
__global__ void k_transpose(const float* __restrict__ w) {
    __shared__ float tile[64][65];
    int bid = blockIdx.x;
    int b = bid >> 6, y = bid & 63;
    int t = threadIdx.x;
    {
        int c = t >> 2, xq = (t & 3) * 16;
        const float4* src = (const float4*)(w + ((((b << 6) | c) << 6 | y) << 6) + xq);
#pragma unroll
        for (int j = 0; j < 4; j++) {
            float4 v = src[j];
            tile[c][xq + 4 * j + 0] = v.x;
            tile[c][xq + 4 * j + 1] = v.y;
            tile[c][xq + 4 * j + 2] = v.z;
            tile[c][xq + 4 * j + 3] = v.w;
        }
    }
    __syncthreads();
    {
        int xx = t >> 2, cq = (t & 3) * 16;
        __half2* dst = (__half2*)(g_wT + ((((size_t)(((b << 6) | y)) << 6 | xx)) << 6) + cq);
#pragma unroll
        for (int j = 0; j < 8; j++)
            dst[j] = __floats2half2_rn(tile[cq + 2 * j][xx], tile[cq + 2 * j + 1][xx]);
    }
}

// ---------------- pack weights into MMA B-fragment order ----------------
__device__ __forceinline__ float getw_(const float* W0, const float* W1,
                                       int net, int layer, int n, int k) {
    if (layer == 0) {
        int oc = -1;
        if (k < 64) oc = 1 + k;
        else if (k < 80) oc = 65 + (k - 64);
        else if (k == 80) oc = 0;
        return (oc >= 0) ? W0[(net * 128 + n) * 81 + oc] : 0.f;
    }
    return W1[((net * 3 + (layer - 1)) * 128 + n) * 128 + k];
}

__global__ void k_packfrag(const float* __restrict__ W0, const float* __restrict__ b0,
                           const float* __restrict__ W1, const float* __restrict__ b1) {
    int idx = blockIdx.x * 256 + threadIdx.x;      // 0..32767
    int gi = idx >> 11;
    int rem = idx & 2047;
    int lane = rem & 31;
    int ks = (rem >> 5) & 7;
    int ntp = (rem >> 8) & 3;
    int colg = (rem >> 10) & 1;
    int net = gi >> 2, layer = gi & 3;
    int gid = lane >> 2, tig = lane & 3;
    int n_even = colg * 64 + ntp * 16 + gid;
    int n_odd  = n_even + 8;
    int k0 = ks * 16 + tig * 2;
    uint4 v;
    v.x = packh2(getw_(W0, W1, net, layer, n_even, k0),     getw_(W0, W1, net, layer, n_even, k0 + 1));
    v.y = packh2(getw_(W0, W1, net, layer, n_even, k0 + 8), getw_(W0, W1, net, layer, n_even, k0 + 9));
    v.z = packh2(getw_(W0, W1, net, layer, n_odd,  k0),     getw_(W0, W1, net, layer, n_odd,  k0 + 1));
    v.w = packh2(getw_(W0, W1, net, layer, n_odd,  k0 + 8), getw_(W0, W1, net, layer, n_odd,  k0 + 9));
    g_wfrag[idx] = v;
    if (idx < 2048) {
        int bn = idx >> 9, bl = (idx >> 7) & 3, bb_ = idx & 127;
        float bv = (bl == 0) ? b0[bn * 128 + bb_]
                             : b1[((bn * 3 + bl - 1) * 128) + bb_];
        g_biasH[idx] = __float2half_rn(bv);
    }
}

// ---------------- fused two-pass coupling kernel ----------------
__global__ void __launch_bounds__(NTHREADS, 2) k_fused(
    const float* __restrict__ x, const float* __restrict__ cond,
    const float* __restrict__ W2, const float* __restrict__ b2,
    float* __restrict__ out) {
    extern __shared__ __align__(16) char smraw[];
    __half* combS  = (__half*)(smraw + OFF_COMB);
    __half* sbiasH = (__half*)(smraw + OFF_BIAS);
    float*  w2s    = (float*)(smraw + OFF_W2);
    float*  spartS = (float*)(smraw + OFF_SPS);
    float*  spartT = (float*)(smraw + OFF_SPT);
    float*  zA     = (float*)(smraw + OFF_ZA);
    float*  sred   = (float*)(smraw + OFF_SRED);

    int tid = threadIdx.x;
    int wid = tid >> 5, lane = tid & 31;
    int gid = lane >> 2, tig = lane & 3;
    int rowg = wid & 3;          // 4 row-groups x 32 tokens = 128
    int colg = wid >> 2;         // 2 col-groups x 64 cols
    int tile = blockIdx.x;

    uint32_t combA = smem_u32(combS);
    uint32_t hexA[2] = {smem_u32(smraw + OFF_HEX0), smem_u32(smraw + OFF_HEX1)};

    // stage biases (all 16 layers) + w2 (all 4 nets)
#pragma unroll
    for (int i = 0; i < 4; i++)
        ((unsigned*)sbiasH)[tid + i * 256] = ((const unsigned*)g_biasH)[tid + i * 256];
    w2s[tid] = __ldg(&W2[tid]);
    w2s[tid + 256] = __ldg(&W2[tid + 256]);

    // ldmatrix per-thread offsets
    int aRow = lane & 15;
    int aK   = (lane >> 4) * 8;
    // stmatrix per-thread offsets: tile i <- lanes 8i..8i+7
    int sti = lane >> 3, str = lane & 7;
    int stRowOff = (sti & 1) * 8;       // row +8 for odd tiles
    int stColOff = (sti >> 1) * 8;      // col +8 halves for tiles 2,3

    unsigned aPack[2][8][2];
    int lastw = 1;   // hEx ping-pong: next write goes to lastw^1

    for (int ps = 0; ps < 2; ps++) {
        // ===== gather + build comb (2 threads per token, LDG.128) =====
        {
            int tk = tid >> 1, p = tid & 1;
            int g0 = tile * TOKPC + tk;
            int b = g0 >> 12;
            float zy = __ldg(&x[g0 * 2 + 1]);
            float zx = (ps == 0) ? __ldg(&x[g0 * 2]) : zA[tk];
            float zkeep = (ps == 0) ? zy : zx;
            float ix = zx * 63.f, iy = zy * 63.f;
            float ix0 = floorf(ix), iy0 = floorf(iy);
            float wx1 = ix - ix0, wx0 = 1.f - wx1;
            float wy1 = iy - iy0, wy0 = 1.f - wy1;
            float acc[32];
#pragma unroll
            for (int i = 0; i < 32; i++) acc[i] = 0.f;
            float cxs[4] = {ix0, ix0 + 1.f, ix0, ix0 + 1.f};
            float cys[4] = {iy0, iy0, iy0 + 1.f, iy0 + 1.f};
            float cws[4] = {wy0 * wx0, wy0 * wx1, wy1 * wx0, wy1 * wx1};
#pragma unroll
            for (int cr = 0; cr < 4; cr++) {
                float xf = cxs[cr], yf = cys[cr], wt = cws[cr];
                if (xf >= 0.f && xf <= 63.f && yf >= 0.f && yf <= 63.f) {
                    int xi = (int)xf, yi = (int)yf;
                    const uint4* src = (const uint4*)((const char*)g_wT +
                        (((size_t)(((b << 6) | yi) << 6 | xi)) << 7) + (p << 6));
#pragma unroll
                    for (int u = 0; u < 4; u++) {
                        uint4 v = __ldg(src + u);
                        unsigned ww[4] = {v.x, v.y, v.z, v.w};
#pragma unroll
                        for (int q = 0; q < 4; q++) {
                            float2 f = __half22float2(*(__half2*)&ww[q]);
                            acc[u * 8 + 2 * q]     += wt * f.x;
                            acc[u * 8 + 2 * q + 1] += wt * f.y;
                        }
                    }
                }
            }
            uint4* dst = (uint4*)((char*)combS + tk * (SC * 2) + p * 64);
#pragma unroll
            for (int u = 0; u < 4; u++) {
                uint4 o;
                o.x = packh2(acc[u * 8 + 0], acc[u * 8 + 1]);
                o.y = packh2(acc[u * 8 + 2], acc[u * 8 + 3]);
                o.z = packh2(acc[u * 8 + 4], acc[u * 8 + 5]);
                o.w = packh2(acc[u * 8 + 6], acc[u * 8 + 7]);
                dst[u] = o;
            }
            __half* crow = combS + tk * SC;
            if (p == 0) {
#pragma unroll
                for (int i = 0; i < 16; i++)
                    crow[64 + i] = __float2half_rn(__ldg(&cond[b * 16 + i]));
                crow[80] = __float2half_rn(zkeep);
#pragma unroll
                for (int cc = 81; cc < 88; cc++) crow[cc] = __float2half_rn(0.f);
            } else {
#pragma unroll
                for (int cc = 88; cc < 96; cc++) crow[cc] = __float2half_rn(0.f);
            }
        }
        __syncthreads();   // comb visible

        // ===== 8 layers of this pass =====
        for (int l = 0; l < 8; l++) {
            int li = ps * 8 + l;
            const uint4* wfB = g_wfrag + ((size_t)li << 11) + (colg << 10) + lane;
            const __half* lbH = sbiasH + li * 128 + 64 * colg;
            int hr = lastw;          // buffer to read (last written)
            int hw = lastw ^ 1;      // buffer to write

            if (l < 4) {
                // ================= s-net: fp32 accumulate =================
                float acc[2][8][4];
#pragma unroll
                for (int mt = 0; mt < 2; mt++)
#pragma unroll
                    for (int nt = 0; nt < 8; nt++)
#pragma unroll
                        for (int q = 0; q < 4; q++) acc[mt][nt][q] = 0.f;

                if (l == 0) {
                    uint32_t a0 = combA + ((32 * rowg + aRow) * SC + aK) * 2;
                    uint32_t a1 = a0 + 16 * SC * 2;
#pragma unroll
                    for (int ks = 0; ks < 6; ks++) {
                        unsigned af0[4], af1[4];
                        ldsm_x4(af0, a0 + ks * 32);
                        ldsm_x4(af1, a1 + ks * 32);
#pragma unroll
                        for (int ntp = 0; ntp < 4; ntp++) {
                            uint4 bf = __ldg(wfB + (ntp * 8 + ks) * 32);
                            mma16816(acc[0][2 * ntp],     af0[0], af0[1], af0[2], af0[3], bf.x, bf.y);
                            mma16816(acc[0][2 * ntp + 1], af0[0], af0[1], af0[2], af0[3], bf.z, bf.w);
                            mma16816(acc[1][2 * ntp],     af1[0], af1[1], af1[2], af1[3], bf.x, bf.y);
                            mma16816(acc[1][2 * ntp + 1], af1[0], af1[1], af1[2], af1[3], bf.z, bf.w);
                        }
                    }
                } else {
                    int pc = colg ^ 1;
                    uint32_t pbase = hexA[hr] + ((32 * rowg + aRow) * SHE + 64 * pc + aK) * 2;
                    int pks0 = 4 * pc, oks0 = 4 * colg;
#pragma unroll
                    for (int q = 0; q < 4; q++) {
                        unsigned af0[4], af1[4];
                        ldsm_x4(af0, pbase + q * 32);
                        ldsm_x4(af1, pbase + 16 * SHE * 2 + q * 32);
#pragma unroll
                        for (int ntp = 0; ntp < 4; ntp++) {
                            uint4 bf = __ldg(wfB + (ntp * 8 + pks0 + q) * 32);
                            mma16816(acc[0][2 * ntp],     af0[0], af0[1], af0[2], af0[3], bf.x, bf.y);
                            mma16816(acc[0][2 * ntp + 1], af0[0], af0[1], af0[2], af0[3], bf.z, bf.w);
                            mma16816(acc[1][2 * ntp],     af1[0], af1[1], af1[2], af1[3], bf.x, bf.y);
                            mma16816(acc[1][2 * ntp + 1], af1[0], af1[1], af1[2], af1[3], bf.z, bf.w);
                        }
                    }
#pragma unroll
                    for (int q = 0; q < 4; q++) {
#pragma unroll
                        for (int ntp = 0; ntp < 4; ntp++) {
                            uint4 bf = __ldg(wfB + (ntp * 8 + oks0 + q) * 32);
                            mma16816(acc[0][2 * ntp], aPack[0][2 * q][0], aPack[0][2 * q][1],
                                     aPack[0][2 * q + 1][0], aPack[0][2 * q + 1][1], bf.x, bf.y);
                            mma16816(acc[0][2 * ntp + 1], aPack[0][2 * q][0], aPack[0][2 * q][1],
                                     aPack[0][2 * q + 1][0], aPack[0][2 * q + 1][1], bf.z, bf.w);
                            mma16816(acc[1][2 * ntp], aPack[1][2 * q][0], aPack[1][2 * q][1],
                                     aPack[1][2 * q + 1][0], aPack[1][2 * q + 1][1], bf.x, bf.y);
                            mma16816(acc[1][2 * ntp + 1], aPack[1][2 * q][0], aPack[1][2 * q][1],
                                     aPack[1][2 * q + 1][0], aPack[1][2 * q + 1][1], bf.z, bf.w);
                        }
                    }
                }

                if (l == 3) {
                    const float* w2 = w2s + ps * 256 + 64 * colg;
#pragma unroll
                    for (int mt = 0; mt < 2; mt++) {
                        float p0 = 0.f, p1 = 0.f;
#pragma unroll
                        for (int nt = 0; nt < 8; nt++) {
                            int c = nt * 8 + tig * 2;
                            float2 bf2 = __half22float2(*(const __half2*)(lbH + c));
                            float w0 = w2[c], w1 = w2[c + 1];
                            p0 += fast_silu(acc[mt][nt][0] + bf2.x) * w0
                                + fast_silu(acc[mt][nt][1] + bf2.y) * w1;
                            p1 += fast_silu(acc[mt][nt][2] + bf2.x) * w0
                                + fast_silu(acc[mt][nt][3] + bf2.y) * w1;
                        }
                        p0 += __shfl_xor_sync(0xffffffffu, p0, 1);
                        p0 += __shfl_xor_sync(0xffffffffu, p0, 2);
                        p1 += __shfl_xor_sync(0xffffffffu, p1, 1);
                        p1 += __shfl_xor_sync(0xffffffffu, p1, 2);
                        if (tig == 0) {
                            spartS[colg * 128 + 32 * rowg + 16 * mt + gid]     = p0;
                            spartS[colg * 128 + 32 * rowg + 16 * mt + gid + 8] = p1;
                        }
                    }
                } else {
#pragma unroll
                    for (int mt = 0; mt < 2; mt++) {
#pragma unroll
                        for (int nt = 0; nt < 8; nt++) {
                            float2 bf2 = __half22float2(*(const __half2*)(lbH + nt * 8 + tig * 2));
                            aPack[mt][nt][0] = packh2(fast_silu(acc[mt][nt][0] + bf2.x),
                                                      fast_silu(acc[mt][nt][1] + bf2.y));
                            aPack[mt][nt][1] = packh2(fast_silu(acc[mt][nt][2] + bf2.x),
                                                      fast_silu(acc[mt][nt][3] + bf2.y));
                        }
                        uint32_t sa = hexA[hw] +
                            ((32 * rowg + 16 * mt + stRowOff + str) * SHE + 64 * colg + stColOff) * 2;
#pragma unroll
                        for (int p = 0; p < 4; p++)
                            stsm_x4(sa + p * 32, aPack[mt][2 * p][0], aPack[mt][2 * p][1],
                                    aPack[mt][2 * p + 1][0], aPack[mt][2 * p + 1][1]);
                    }
                    lastw = hw;
                }
            } else {
                // ================= t-net: fp16 accumulate =================
                unsigned acch[2][8][2];
#pragma unroll
                for (int mt = 0; mt < 2; mt++)
#pragma unroll
                    for (int nt = 0; nt < 8; nt++) { acch[mt][nt][0] = 0u; acch[mt][nt][1] = 0u; }

                if (l == 4) {
                    uint32_t a0 = combA + ((32 * rowg + aRow) * SC + aK) * 2;
                    uint32_t a1 = a0 + 16 * SC * 2;
#pragma unroll
                    for (int ks = 0; ks < 6; ks++) {
                        unsigned af0[4], af1[4];
                        ldsm_x4(af0, a0 + ks * 32);
                        ldsm_x4(af1, a1 + ks * 32);
#pragma unroll
                        for (int ntp = 0; ntp < 4; ntp++) {
                            uint4 bf = __ldg(wfB + (ntp * 8 + ks) * 32);
                            mma16816h(acch[0][2 * ntp],     af0[0], af0[1], af0[2], af0[3], bf.x, bf.y);
                            mma16816h(acch[0][2 * ntp + 1], af0[0], af0[1], af0[2], af0[3], bf.z, bf.w);
                            mma16816h(acch[1][2 * ntp],     af1[0], af1[1], af1[2], af1[3], bf.x, bf.y);
                            mma16816h(acch[1][2 * ntp + 1], af1[0], af1[1], af1[2], af1[3], bf.z, bf.w);
                        }
                    }
                } else {
                    int pc = colg ^ 1;
                    uint32_t pbase = hexA[hr] + ((32 * rowg + aRow) * SHE + 64 * pc + aK) * 2;
                    int pks0 = 4 * pc, oks0 = 4 * colg;
#pragma unroll
                    for (int q = 0; q < 4; q++) {
                        unsigned af0[4], af1[4];
                        ldsm_x4(af0, pbase + q * 32);
                        ldsm_x4(af1, pbase + 16 * SHE * 2 + q * 32);
#pragma unroll
                        for (int ntp = 0; ntp < 4; ntp++) {
                            uint4 bf = __ldg(wfB + (ntp * 8 + pks0 + q) * 32);
                            mma16816h(acch[0][2 * ntp],     af0[0], af0[1], af0[2], af0[3], bf.x, bf.y);
                            mma16816h(acch[0][2 * ntp + 1], af0[0], af0[1], af0[2], af0[3], bf.z, bf.w);
                            mma16816h(acch[1][2 * ntp],     af1[0], af1[1], af1[2], af1[3], bf.x, bf.y);
                            mma16816h(acch[1][2 * ntp + 1], af1[0], af1[1], af1[2], af1[3], bf.z, bf.w);
                        }
                    }
#pragma unroll
                    for (int q = 0; q < 4; q++) {
#pragma unroll
                        for (int ntp = 0; ntp < 4; ntp++) {
                            uint4 bf = __ldg(wfB + (ntp * 8 + oks0 + q) * 32);
                            mma16816h(acch[0][2 * ntp], aPack[0][2 * q][0], aPack[0][2 * q][1],
                                      aPack[0][2 * q + 1][0], aPack[0][2 * q + 1][1], bf.x, bf.y);
                            mma16816h(acch[0][2 * ntp + 1], aPack[0][2 * q][0], aPack[0][2 * q][1],
                                      aPack[0][2 * q + 1][0], aPack[0][2 * q + 1][1], bf.z, bf.w);
                            mma16816h(acch[1][2 * ntp], aPack[1][2 * q][0], aPack[1][2 * q][1],
                                      aPack[1][2 * q + 1][0], aPack[1][2 * q + 1][1], bf.x, bf.y);
                            mma16816h(acch[1][2 * ntp + 1], aPack[1][2 * q][0], aPack[1][2 * q][1],
                                      aPack[1][2 * q + 1][0], aPack[1][2 * q + 1][1], bf.z, bf.w);
                        }
                    }
                }

                if (l == 7) {
                    const float* w2 = w2s + ps * 256 + 128 + 64 * colg;
#pragma unroll
                    for (int mt = 0; mt < 2; mt++) {
                        float p0 = 0.f, p1 = 0.f;
#pragma unroll
                        for (int nt = 0; nt < 8; nt++) {
                            int c = nt * 8 + tig * 2;
                            __half2 bias = *(const __half2*)(lbH + c);
                            float w0 = w2[c], w1 = w2[c + 1];
                            float2 f0 = __half22float2(silu_h2h(__hadd2(*(__half2*)&acch[mt][nt][0], bias)));
                            float2 f1 = __half22float2(silu_h2h(__hadd2(*(__half2*)&acch[mt][nt][1], bias)));
                            p0 += f0.x * w0 + f0.y * w1;
                            p1 += f1.x * w0 + f1.y * w1;
                        }
                        p0 += __shfl_xor_sync(0xffffffffu, p0, 1);
                        p0 += __shfl_xor_sync(0xffffffffu, p0, 2);
                        p1 += __shfl_xor_sync(0xffffffffu, p1, 1);
                        p1 += __shfl_xor_sync(0xffffffffu, p1, 2);
                        if (tig == 0) {
                            spartT[colg * 128 + 32 * rowg + 16 * mt + gid]     = p0;
                            spartT[colg * 128 + 32 * rowg + 16 * mt + gid + 8] = p1;
                        }
                    }
                } else {
#pragma unroll
                    for (int mt = 0; mt < 2; mt++) {
#pragma unroll
                        for (int nt = 0; nt < 8; nt++) {
                            __half2 bias = *(const __half2*)(lbH + nt * 8 + tig * 2);
                            __half2 h0 = silu_h2h(__hadd2(*(__half2*)&acch[mt][nt][0], bias));
                            __half2 h1 = silu_h2h(__hadd2(*(__half2*)&acch[mt][nt][1], bias));
                            aPack[mt][nt][0] = *(unsigned*)&h0;
                            aPack[mt][nt][1] = *(unsigned*)&h1;
                        }
                        uint32_t sa = hexA[hw] +
                            ((32 * rowg + 16 * mt + stRowOff + str) * SHE + 64 * colg + stColOff) * 2;
#pragma unroll
                        for (int p = 0; p < 4; p++)
                            stsm_x4(sa + p * 32, aPack[mt][2 * p][0], aPack[mt][2 * p][1],
                                    aPack[mt][2 * p + 1][0], aPack[mt][2 * p + 1][1]);
                    }
                    lastw = hw;
                }
            }

            __syncthreads();   // hEx writes visible; prior hEx/comb reads complete
        }

        // ===== coupling epilogue for this pass =====
        if (tid < TOKPC) {
            int g0 = tile * TOKPC + tid;
            float zold = (ps == 0) ? __ldg(&x[g0 * 2]) : __ldg(&x[g0 * 2 + 1]);
            float s_lin = spartS[tid] + spartS[128 + tid] + __ldg(&b2[ps * 2]);
            float t_lin = spartT[tid] + spartT[128 + tid] + __ldg(&b2[ps * 2 + 1]);
            float sv = tanhf(s_lin) * 1.5f;
            float z = zold * __expf(sv) + t_lin;
            out[g0 * 2 + ps] = z;
            if (ps == 0) { zA[tid] = z; sred[tid] = sv; }
            else sred[tid] += sv;
        }
        __syncthreads();
    }

    // ===== deterministic block reduce of s (both passes) =====
    if (tid < 64) sred[tid] += sred[tid + 64];
    __syncthreads();
    if (tid < 32) {
        float v = sred[tid] + sred[tid + 32];
#pragma unroll
        for (int off = 16; off; off >>= 1) v += __shfl_xor_sync(0xffffffffu, v, off);
        if (tid == 0) g_part[tile] = v;
    }
}

// ---------------- log-det reduce ----------------
__global__ void k_reduce(float* __restrict__ out) {
    int b = threadIdx.x;
    if (b < BB) {
        float acc = 0.f;
        for (int i = 0; i < 32; i++)
            acc += g_part[b * 32 + i];
        out[(size_t)NTOK * 2 + b] = acc;
    }
}

// ---------------- launcher ----------------
extern "C" void kernel_launch(void* const* d_in, const int* in_sizes, int n_in,
                              void* d_out, int out_size) {
    const float* x    = (const float*)d_in[0];
    const float* w    = (const float*)d_in[1];
    const float* cond = (const float*)d_in[2];
    const float* W0   = (const float*)d_in[3];
    const float* b0   = (const float*)d_in[4];
    const float* W1   = (const float*)d_in[5];
    const float* b1   = (const float*)d_in[6];
    const float* W2   = (const float*)d_in[7];
    const float* b2   = (const float*)d_in[8];
    float* out = (float*)d_out;

    cudaFuncSetAttribute(k_fused, cudaFuncAttributeMaxDynamicSharedMemorySize, SMEM_TOT);

    k_transpose<<<4096, 256>>>(w);
    k_packfrag<<<128, 256>>>(W0, b0, W1, b1);
    k_fused<<<NCTAS, NTHREADS, SMEM_TOT>>>(x, cond, W2, b2, out);
    k_reduce<<<1, 64>>>(out);
}

// round 16
// speedup vs baseline: 1.3962x; 1.0516x over previous
#include <cuda_runtime.h>
#include <cuda_fp16.h>
#include <stdint.h>

// Problem dims
#define BB   64
#define TT   4096
#define NTOK (BB*TT)          // 262144
#define TOKPC 64              // tokens per CTA
#define NCTAS (NTOK/TOKPC)    // 4096
#define NTHREADS 128

// smem strides (halves): row stride in 16B units coprime with 8 -> LDSM/STSM conflict-free
#define SC  104               // comb stride (K=96 padded)
#define SHE 136               // hidden-exchange stride

// smem byte offsets
#define OFF_COMB   0                  // 64*SC*2  = 13312
#define OFF_HEX    13312              // 64*SHE*2 = 17408
#define OFF_BIAS   30720              // 2048 halves = 4096
#define OFF_W2     34816              // 512 floats  = 2048
#define OFF_SPS    36864              // 128 floats  = 512
#define OFF_SPT    37376              // 128 floats  = 512
#define OFF_ZA     37888              // 64 floats   = 256
#define OFF_SRED   38144              // 64 floats   = 256
#define SMEM_TOT   38400

// ---------------- device scratch ----------------
__device__ __align__(16) __half g_wT[(size_t)BB * 64 * 64 * 64]; // [b][y][x][c] fp16, 32MB
__device__ __align__(16) uint4 g_wfrag[16 * 2048];               // [li][colg][ntp][ks][lane]
__device__ __align__(4) __half g_biasH[4 * 4 * 128];             // [net][layer][n] fp16
__device__ float g_part[NCTAS];                                  // per-tile s-sums

// ---------------- helpers ----------------
__device__ __forceinline__ void mma16816(float c[4], const unsigned a0, const unsigned a1,
                                         const unsigned a2, const unsigned a3,
                                         unsigned b0, unsigned b1) {
    asm volatile(
        "mma.sync.aligned.m16n8k16.row.col.f32.f16.f16.f32 "
        "{%0,%1,%2,%3}, {%4,%5,%6,%7}, {%8,%9}, {%0,%1,%2,%3};"
        : "+f"(c[0]), "+f"(c[1]), "+f"(c[2]), "+f"(c[3])
        : "r"(a0), "r"(a1), "r"(a2), "r"(a3), "r"(b0), "r"(b1));
}

__device__ __forceinline__ void mma16816h(unsigned c[2], const unsigned a0, const unsigned a1,
                                          const unsigned a2, const unsigned a3,
                                          unsigned b0, unsigned b1) {
    asm volatile(
        "mma.sync.aligned.m16n8k16.row.col.f16.f16.f16.f16 "
        "{%0,%1}, {%2,%3,%4,%5}, {%6,%7}, {%0,%1};"
        : "+r"(c[0]), "+r"(c[1])
        : "r"(a0), "r"(a1), "r"(a2), "r"(a3), "r"(b0), "r"(b1));
}

__device__ __forceinline__ void ldsm_x4(unsigned r[4], uint32_t addr) {
    asm volatile("ldmatrix.sync.aligned.m8n8.x4.shared.b16 {%0,%1,%2,%3}, [%4];"
                 : "=r"(r[0]), "=r"(r[1]), "=r"(r[2]), "=r"(r[3]) : "r"(addr));
}

__device__ __forceinline__ void stsm_x4(uint32_t addr, unsigned r0, unsigned r1,
                                        unsigned r2, unsigned r3) {
    asm volatile("stmatrix.sync.aligned.m8n8.x4.shared.b16 [%0], {%1,%2,%3,%4};"
                 :: "r"(addr), "r"(r0), "r"(r1), "r"(r2), "r"(r3) : "memory");
}

__device__ __forceinline__ uint32_t smem_u32(const void* p) {
    uint32_t a;
    asm("{ .reg .u64 t; cvta.to.shared.u64 t, %1; cvt.u32.u64 %0, t; }" : "=r"(a) : "l"(p));
    return a;
}

__device__ __forceinline__ float fast_silu(float v) {
    float t;
    asm("tanh.approx.f32 %0, %1;" : "=f"(t) : "f"(0.5f * v));
    return 0.5f * v * (t + 1.0f);
}
__device__ __forceinline__ unsigned packh2(float a, float b) {
    __half2 h = __floats2half2_rn(a, b);
    return *(unsigned*)&h;
}
__device__ __forceinline__ __half2 silu_h2h(__half2 p) {
    __half2 u = __hmul2(p, __float2half2_rn(0.5f));
    __half2 t;
    asm("tanh.approx.f16x2 %0, %1;" : "=r"(*(unsigned*)&t) : "r"(*(unsigned*)&u));
    return __hfma2(u, t, u);
}

// ---------------- transpose w[B,C,H,W] f32 -> wT[b][y][x][c] fp16 ----------------
__global__ void k_transpose(const float* __restrict__ w) {
    __shared__ float tile[64][65];
    int bid = blockIdx.x;
    int b = bid >> 6, y = bid & 63;
    int t = threadIdx.x;
    {
        int c = t >> 2, xq = (t & 3) * 16;
        const float4* src = (const float4*)(w + ((((b << 6) | c) << 6 | y) << 6) + xq);
#pragma unroll
        for (int j = 0; j < 4; j++) {
            float4 v = src[j];
            tile[c][xq + 4 * j + 0] = v.x;
            tile[c][xq + 4 * j + 1] = v.y;
            tile[c][xq + 4 * j + 2] = v.z;
            tile[c][xq + 4 * j + 3] = v.w;
        }
    }
    __syncthreads();
    {
        int xx = t >> 2, cq = (t & 3) * 16;
        __half2* dst = (__half2*)(g_wT + ((((size_t)(((b << 6) | y)) << 6 | xx)) << 6) + cq);
#pragma unroll
        for (int j = 0; j < 8; j++)
            dst[j] = __floats2half2_rn(tile[cq + 2 * j][xx], tile[cq + 2 * j + 1][xx]);
    }
}

// ---------------- pack weights into MMA B-fragment order ----------------
__device__ __forceinline__ float getw_(const float* W0, const float* W1,
                                       int net, int layer, int n, int k) {
    if (layer == 0) {
        int oc = -1;
        if (k < 64) oc = 1 + k;
        else if (k < 80) oc = 65 + (k - 64);
        else if (k == 80) oc = 0;
        return (oc >= 0) ? W0[(net * 128 + n) * 81 + oc] : 0.f;
    }
    return W1[((net * 3 + (layer - 1)) * 128 + n) * 128 + k];
}

__global__ void k_packfrag(const float* __restrict__ W0, const float* __restrict__ b0,
                           const float* __restrict__ W1, const float* __restrict__ b1) {
    int idx = blockIdx.x * 256 + threadIdx.x;      // 0..32767
    int gi = idx >> 11;
    int rem = idx & 2047;
    int lane = rem & 31;
    int ks = (rem >> 5) & 7;
    int ntp = (rem >> 8) & 3;
    int colg = (rem >> 10) & 1;
    int net = gi >> 2, layer = gi & 3;
    int gid = lane >> 2, tig = lane & 3;
    int n_even = colg * 64 + ntp * 16 + gid;
    int n_odd  = n_even + 8;
    int k0 = ks * 16 + tig * 2;
    uint4 v;
    v.x = packh2(getw_(W0, W1, net, layer, n_even, k0),     getw_(W0, W1, net, layer, n_even, k0 + 1));
    v.y = packh2(getw_(W0, W1, net, layer, n_even, k0 + 8), getw_(W0, W1, net, layer, n_even, k0 + 9));
    v.z = packh2(getw_(W0, W1, net, layer, n_odd,  k0),     getw_(W0, W1, net, layer, n_odd,  k0 + 1));
    v.w = packh2(getw_(W0, W1, net, layer, n_odd,  k0 + 8), getw_(W0, W1, net, layer, n_odd,  k0 + 9));
    g_wfrag[idx] = v;
    if (idx < 2048) {
        int bn = idx >> 9, bl = (idx >> 7) & 3, bb_ = idx & 127;
        float bv = (bl == 0) ? b0[bn * 128 + bb_]
                             : b1[((bn * 3 + bl - 1) * 128) + bb_];
        g_biasH[idx] = __float2half_rn(bv);
    }
}

// ---------------- fused two-pass coupling kernel: 64 tok/CTA, 4 CTAs/SM ----------------
__global__ void __launch_bounds__(NTHREADS, 4) k_fused(
    const float* __restrict__ x, const float* __restrict__ cond,
    const float* __restrict__ W2, const float* __restrict__ b2,
    float* __restrict__ out) {
    extern __shared__ __align__(16) char smraw[];
    __half* combS  = (__half*)(smraw + OFF_COMB);
    __half* sbiasH = (__half*)(smraw + OFF_BIAS);
    float*  w2s    = (float*)(smraw + OFF_W2);
    float*  spartS = (float*)(smraw + OFF_SPS);
    float*  spartT = (float*)(smraw + OFF_SPT);
    float*  zA     = (float*)(smraw + OFF_ZA);
    float*  sred   = (float*)(smraw + OFF_SRED);

    int tid = threadIdx.x;
    int wid = tid >> 5, lane = tid & 31;
    int gid = lane >> 2, tig = lane & 3;
    int rowg = wid & 1;          // 2 row-groups x 32 tokens = 64
    int colg = wid >> 1;         // 2 col-groups x 64 cols
    int tile = blockIdx.x;

    uint32_t combA = smem_u32(combS);
    uint32_t hExA  = smem_u32(smraw + OFF_HEX);

    // stage biases (all 16 layers) + w2 (all 4 nets)
#pragma unroll
    for (int i = 0; i < 8; i++)
        ((unsigned*)sbiasH)[tid + i * 128] = ((const unsigned*)g_biasH)[tid + i * 128];
#pragma unroll
    for (int i = 0; i < 4; i++)
        w2s[tid + i * 128] = __ldg(&W2[tid + i * 128]);

    // ldmatrix per-thread offsets
    int aRow = lane & 15;
    int aK   = (lane >> 4) * 8;
    // stmatrix per-thread offsets: tile i <- lanes 8i..8i+7
    int sti = lane >> 3, str = lane & 7;
    int stRowOff = (sti & 1) * 8;
    int stColOff = (sti >> 1) * 8;

    unsigned aPack[2][8][2];

    for (int ps = 0; ps < 2; ps++) {
        // ===== gather + build comb (2 threads per token, LDG.128) =====
        {
            int tk = tid >> 1, p = tid & 1;
            int g0 = tile * TOKPC + tk;
            int b = g0 >> 12;
            float zy = __ldg(&x[g0 * 2 + 1]);
            float zx = (ps == 0) ? __ldg(&x[g0 * 2]) : zA[tk];
            float zkeep = (ps == 0) ? zy : zx;
            float ix = zx * 63.f, iy = zy * 63.f;
            float ix0 = floorf(ix), iy0 = floorf(iy);
            float wx1 = ix - ix0, wx0 = 1.f - wx1;
            float wy1 = iy - iy0, wy0 = 1.f - wy1;
            float acc[32];
#pragma unroll
            for (int i = 0; i < 32; i++) acc[i] = 0.f;
            float cxs[4] = {ix0, ix0 + 1.f, ix0, ix0 + 1.f};
            float cys[4] = {iy0, iy0, iy0 + 1.f, iy0 + 1.f};
            float cws[4] = {wy0 * wx0, wy0 * wx1, wy1 * wx0, wy1 * wx1};
#pragma unroll
            for (int cr = 0; cr < 4; cr++) {
                float xf = cxs[cr], yf = cys[cr], wt = cws[cr];
                if (xf >= 0.f && xf <= 63.f && yf >= 0.f && yf <= 63.f) {
                    int xi = (int)xf, yi = (int)yf;
                    const uint4* src = (const uint4*)((const char*)g_wT +
                        (((size_t)(((b << 6) | yi) << 6 | xi)) << 7) + (p << 6));
#pragma unroll
                    for (int u = 0; u < 4; u++) {
                        uint4 v = __ldg(src + u);
                        unsigned ww[4] = {v.x, v.y, v.z, v.w};
#pragma unroll
                        for (int q = 0; q < 4; q++) {
                            float2 f = __half22float2(*(__half2*)&ww[q]);
                            acc[u * 8 + 2 * q]     += wt * f.x;
                            acc[u * 8 + 2 * q + 1] += wt * f.y;
                        }
                    }
                }
            }
            uint4* dst = (uint4*)((char*)combS + tk * (SC * 2) + p * 64);
#pragma unroll
            for (int u = 0; u < 4; u++) {
                uint4 o;
                o.x = packh2(acc[u * 8 + 0], acc[u * 8 + 1]);
                o.y = packh2(acc[u * 8 + 2], acc[u * 8 + 3]);
                o.z = packh2(acc[u * 8 + 4], acc[u * 8 + 5]);
                o.w = packh2(acc[u * 8 + 6], acc[u * 8 + 7]);
                dst[u] = o;
            }
            __half* crow = combS + tk * SC;
            if (p == 0) {
#pragma unroll
                for (int i = 0; i < 16; i++)
                    crow[64 + i] = __float2half_rn(__ldg(&cond[b * 16 + i]));
                crow[80] = __float2half_rn(zkeep);
#pragma unroll
                for (int cc = 81; cc < 88; cc++) crow[cc] = __float2half_rn(0.f);
            } else {
#pragma unroll
                for (int cc = 88; cc < 96; cc++) crow[cc] = __float2half_rn(0.f);
            }
        }
        __syncthreads();   // comb visible

        // ===== 8 layers of this pass (single hEx buffer, 2 syncs/layer) =====
        for (int l = 0; l < 8; l++) {
            int li = ps * 8 + l;
            const uint4* wfB = g_wfrag + ((size_t)li << 11) + (colg << 10) + lane;
            const __half* lbH = sbiasH + li * 128 + 64 * colg;

            if (l < 4) {
                // ================= s-net: fp32 accumulate =================
                float acc[2][8][4];
#pragma unroll
                for (int mt = 0; mt < 2; mt++)
#pragma unroll
                    for (int nt = 0; nt < 8; nt++)
#pragma unroll
                        for (int q = 0; q < 4; q++) acc[mt][nt][q] = 0.f;

                if (l == 0) {
                    uint32_t a0 = combA + ((32 * rowg + aRow) * SC + aK) * 2;
                    uint32_t a1 = a0 + 16 * SC * 2;
#pragma unroll
                    for (int ks = 0; ks < 6; ks++) {
                        unsigned af0[4], af1[4];
                        ldsm_x4(af0, a0 + ks * 32);
                        ldsm_x4(af1, a1 + ks * 32);
#pragma unroll
                        for (int ntp = 0; ntp < 4; ntp++) {
                            uint4 bf = __ldg(wfB + (ntp * 8 + ks) * 32);
                            mma16816(acc[0][2 * ntp],     af0[0], af0[1], af0[2], af0[3], bf.x, bf.y);
                            mma16816(acc[0][2 * ntp + 1], af0[0], af0[1], af0[2], af0[3], bf.z, bf.w);
                            mma16816(acc[1][2 * ntp],     af1[0], af1[1], af1[2], af1[3], bf.x, bf.y);
                            mma16816(acc[1][2 * ntp + 1], af1[0], af1[1], af1[2], af1[3], bf.z, bf.w);
                        }
                    }
                } else {
                    int pc = colg ^ 1;
                    uint32_t pbase = hExA + ((32 * rowg + aRow) * SHE + 64 * pc + aK) * 2;
                    int pks0 = 4 * pc, oks0 = 4 * colg;
#pragma unroll
                    for (int q = 0; q < 4; q++) {
                        unsigned af0[4], af1[4];
                        ldsm_x4(af0, pbase + q * 32);
                        ldsm_x4(af1, pbase + 16 * SHE * 2 + q * 32);
#pragma unroll
                        for (int ntp = 0; ntp < 4; ntp++) {
                            uint4 bf = __ldg(wfB + (ntp * 8 + pks0 + q) * 32);
                            mma16816(acc[0][2 * ntp],     af0[0], af0[1], af0[2], af0[3], bf.x, bf.y);
                            mma16816(acc[0][2 * ntp + 1], af0[0], af0[1], af0[2], af0[3], bf.z, bf.w);
                            mma16816(acc[1][2 * ntp],     af1[0], af1[1], af1[2], af1[3], bf.x, bf.y);
                            mma16816(acc[1][2 * ntp + 1], af1[0], af1[1], af1[2], af1[3], bf.z, bf.w);
                        }
                    }
#pragma unroll
                    for (int q = 0; q < 4; q++) {
#pragma unroll
                        for (int ntp = 0; ntp < 4; ntp++) {
                            uint4 bf = __ldg(wfB + (ntp * 8 + oks0 + q) * 32);
                            mma16816(acc[0][2 * ntp], aPack[0][2 * q][0], aPack[0][2 * q][1],
                                     aPack[0][2 * q + 1][0], aPack[0][2 * q + 1][1], bf.x, bf.y);
                            mma16816(acc[0][2 * ntp + 1], aPack[0][2 * q][0], aPack[0][2 * q][1],
                                     aPack[0][2 * q + 1][0], aPack[0][2 * q + 1][1], bf.z, bf.w);
                            mma16816(acc[1][2 * ntp], aPack[1][2 * q][0], aPack[1][2 * q][1],
                                     aPack[1][2 * q + 1][0], aPack[1][2 * q + 1][1], bf.x, bf.y);
                            mma16816(acc[1][2 * ntp + 1], aPack[1][2 * q][0], aPack[1][2 * q][1],
                                     aPack[1][2 * q + 1][0], aPack[1][2 * q + 1][1], bf.z, bf.w);
                        }
                    }
                }

                __syncthreads();   // hEx reads complete before rewrite

                if (l == 3) {
                    const float* w2 = w2s + ps * 256 + 64 * colg;
#pragma unroll
                    for (int mt = 0; mt < 2; mt++) {
                        float p0 = 0.f, p1 = 0.f;
#pragma unroll
                        for (int nt = 0; nt < 8; nt++) {
                            int c = nt * 8 + tig * 2;
                            float2 bf2 = __half22float2(*(const __half2*)(lbH + c));
                            float w0 = w2[c], w1 = w2[c + 1];
                            p0 += fast_silu(acc[mt][nt][0] + bf2.x) * w0
                                + fast_silu(acc[mt][nt][1] + bf2.y) * w1;
                            p1 += fast_silu(acc[mt][nt][2] + bf2.x) * w0
                                + fast_silu(acc[mt][nt][3] + bf2.y) * w1;
                        }
                        p0 += __shfl_xor_sync(0xffffffffu, p0, 1);
                        p0 += __shfl_xor_sync(0xffffffffu, p0, 2);
                        p1 += __shfl_xor_sync(0xffffffffu, p1, 1);
                        p1 += __shfl_xor_sync(0xffffffffu, p1, 2);
                        if (tig == 0) {
                            spartS[colg * 64 + 32 * rowg + 16 * mt + gid]     = p0;
                            spartS[colg * 64 + 32 * rowg + 16 * mt + gid + 8] = p1;
                        }
                    }
                } else {
#pragma unroll
                    for (int mt = 0; mt < 2; mt++) {
#pragma unroll
                        for (int nt = 0; nt < 8; nt++) {
                            float2 bf2 = __half22float2(*(const __half2*)(lbH + nt * 8 + tig * 2));
                            aPack[mt][nt][0] = packh2(fast_silu(acc[mt][nt][0] + bf2.x),
                                                      fast_silu(acc[mt][nt][1] + bf2.y));
                            aPack[mt][nt][1] = packh2(fast_silu(acc[mt][nt][2] + bf2.x),
                                                      fast_silu(acc[mt][nt][3] + bf2.y));
                        }
                        uint32_t sa = hExA +
                            ((32 * rowg + 16 * mt + stRowOff + str) * SHE + 64 * colg + stColOff) * 2;
#pragma unroll
                        for (int p = 0; p < 4; p++)
                            stsm_x4(sa + p * 32, aPack[mt][2 * p][0], aPack[mt][2 * p][1],
                                    aPack[mt][2 * p + 1][0], aPack[mt][2 * p + 1][1]);
                    }
                }
            } else {
                // ================= t-net: fp16 accumulate =================
                unsigned acch[2][8][2];
#pragma unroll
                for (int mt = 0; mt < 2; mt++)
#pragma unroll
                    for (int nt = 0; nt < 8; nt++) { acch[mt][nt][0] = 0u; acch[mt][nt][1] = 0u; }

                if (l == 4) {
                    uint32_t a0 = combA + ((32 * rowg + aRow) * SC + aK) * 2;
                    uint32_t a1 = a0 + 16 * SC * 2;
#pragma unroll
                    for (int ks = 0; ks < 6; ks++) {
                        unsigned af0[4], af1[4];
                        ldsm_x4(af0, a0 + ks * 32);
                        ldsm_x4(af1, a1 + ks * 32);
#pragma unroll
                        for (int ntp = 0; ntp < 4; ntp++) {
                            uint4 bf = __ldg(wfB + (ntp * 8 + ks) * 32);
                            mma16816h(acch[0][2 * ntp],     af0[0], af0[1], af0[2], af0[3], bf.x, bf.y);
                            mma16816h(acch[0][2 * ntp + 1], af0[0], af0[1], af0[2], af0[3], bf.z, bf.w);
                            mma16816h(acch[1][2 * ntp],     af1[0], af1[1], af1[2], af1[3], bf.x, bf.y);
                            mma16816h(acch[1][2 * ntp + 1], af1[0], af1[1], af1[2], af1[3], bf.z, bf.w);
                        }
                    }
                } else {
                    int pc = colg ^ 1;
                    uint32_t pbase = hExA + ((32 * rowg + aRow) * SHE + 64 * pc + aK) * 2;
                    int pks0 = 4 * pc, oks0 = 4 * colg;
#pragma unroll
                    for (int q = 0; q < 4; q++) {
                        unsigned af0[4], af1[4];
                        ldsm_x4(af0, pbase + q * 32);
                        ldsm_x4(af1, pbase + 16 * SHE * 2 + q * 32);
#pragma unroll
                        for (int ntp = 0; ntp < 4; ntp++) {
                            uint4 bf = __ldg(wfB + (ntp * 8 + pks0 + q) * 32);
                            mma16816h(acch[0][2 * ntp],     af0[0], af0[1], af0[2], af0[3], bf.x, bf.y);
                            mma16816h(acch[0][2 * ntp + 1], af0[0], af0[1], af0[2], af0[3], bf.z, bf.w);
                            mma16816h(acch[1][2 * ntp],     af1[0], af1[1], af1[2], af1[3], bf.x, bf.y);
                            mma16816h(acch[1][2 * ntp + 1], af1[0], af1[1], af1[2], af1[3], bf.z, bf.w);
                        }
                    }
#pragma unroll
                    for (int q = 0; q < 4; q++) {
#pragma unroll
                        for (int ntp = 0; ntp < 4; ntp++) {
                            uint4 bf = __ldg(wfB + (ntp * 8 + oks0 + q) * 32);
                            mma16816h(acch[0][2 * ntp], aPack[0][2 * q][0], aPack[0][2 * q][1],
                                      aPack[0][2 * q + 1][0], aPack[0][2 * q + 1][1], bf.x, bf.y);
                            mma16816h(acch[0][2 * ntp + 1], aPack[0][2 * q][0], aPack[0][2 * q][1],
                                      aPack[0][2 * q + 1][0], aPack[0][2 * q + 1][1], bf.z, bf.w);
                            mma16816h(acch[1][2 * ntp], aPack[1][2 * q][0], aPack[1][2 * q][1],
                                      aPack[1][2 * q + 1][0], aPack[1][2 * q + 1][1], bf.x, bf.y);
                            mma16816h(acch[1][2 * ntp + 1], aPack[1][2 * q][0], aPack[1][2 * q][1],
                                      aPack[1][2 * q + 1][0], aPack[1][2 * q + 1][1], bf.z, bf.w);
                        }
                    }
                }

                __syncthreads();   // hEx reads complete before rewrite

                if (l == 7) {
                    const float* w2 = w2s + ps * 256 + 128 + 64 * colg;
#pragma unroll
                    for (int mt = 0; mt < 2; mt++) {
                        float p0 = 0.f, p1 = 0.f;
#pragma unroll
                        for (int nt = 0; nt < 8; nt++) {
                            int c = nt * 8 + tig * 2;
                            __half2 bias = *(const __half2*)(lbH + c);
                            float w0 = w2[c], w1 = w2[c + 1];
                            float2 f0 = __half22float2(silu_h2h(__hadd2(*(__half2*)&acch[mt][nt][0], bias)));
                            float2 f1 = __half22float2(silu_h2h(__hadd2(*(__half2*)&acch[mt][nt][1], bias)));
                            p0 += f0.x * w0 + f0.y * w1;
                            p1 += f1.x * w0 + f1.y * w1;
                        }
                        p0 += __shfl_xor_sync(0xffffffffu, p0, 1);
                        p0 += __shfl_xor_sync(0xffffffffu, p0, 2);
                        p1 += __shfl_xor_sync(0xffffffffu, p1, 1);
                        p1 += __shfl_xor_sync(0xffffffffu, p1, 2);
                        if (tig == 0) {
                            spartT[colg * 64 + 32 * rowg + 16 * mt + gid]     = p0;
                            spartT[colg * 64 + 32 * rowg + 16 * mt + gid + 8] = p1;
                        }
                    }
                } else {
#pragma unroll
                    for (int mt = 0; mt < 2; mt++) {
#pragma unroll
                        for (int nt = 0; nt < 8; nt++) {
                            __half2 bias = *(const __half2*)(lbH + nt * 8 + tig * 2);
                            __half2 h0 = silu_h2h(__hadd2(*(__half2*)&acch[mt][nt][0], bias));
                            __half2 h1 = silu_h2h(__hadd2(*(__half2*)&acch[mt][nt][1], bias));
                            aPack[mt][nt][0] = *(unsigned*)&h0;
                            aPack[mt][nt][1] = *(unsigned*)&h1;
                        }
                        uint32_t sa = hExA +
                            ((32 * rowg + 16 * mt + stRowOff + str) * SHE + 64 * colg + stColOff) * 2;
#pragma unroll
                        for (int p = 0; p < 4; p++)
                            stsm_x4(sa + p * 32, aPack[mt][2 * p][0], aPack[mt][2 * p][1],
                                    aPack[mt][2 * p + 1][0], aPack[mt][2 * p + 1][1]);
                    }
                }
            }

            __syncthreads();   // hEx writes visible to next layer
        }

        // ===== coupling epilogue for this pass =====
        if (tid < TOKPC) {
            int g0 = tile * TOKPC + tid;
            float zold = (ps == 0) ? __ldg(&x[g0 * 2]) : __ldg(&x[g0 * 2 + 1]);
            float s_lin = spartS[tid] + spartS[64 + tid] + __ldg(&b2[ps * 2]);
            float t_lin = spartT[tid] + spartT[64 + tid] + __ldg(&b2[ps * 2 + 1]);
            float sv = tanhf(s_lin) * 1.5f;
            float z = zold * __expf(sv) + t_lin;
            out[g0 * 2 + ps] = z;
            if (ps == 0) { zA[tid] = z; sred[tid] = sv; }
            else sred[tid] += sv;
        }
        __syncthreads();
    }

    // ===== deterministic block reduce of s (both passes) =====
    if (tid < 32) {
        float v = sred[tid] + sred[tid + 32];
#pragma unroll
        for (int off = 16; off; off >>= 1) v += __shfl_xor_sync(0xffffffffu, v, off);
        if (tid == 0) g_part[tile] = v;
    }
}

// ---------------- log-det reduce ----------------
__global__ void k_reduce(float* __restrict__ out) {
    int b = threadIdx.x;
    if (b < BB) {
        float acc = 0.f;
        for (int i = 0; i < 64; i++)
            acc += g_part[b * 64 + i];
        out[(size_t)NTOK * 2 + b] = acc;
    }
}

// ---------------- launcher ----------------
extern "C" void kernel_launch(void* const* d_in, const int* in_sizes, int n_in,
                              void* d_out, int out_size) {
    const float* x    = (const float*)d_in[0];
    const float* w    = (const float*)d_in[1];
    const float* cond = (const float*)d_in[2];
    const float* W0   = (const float*)d_in[3];
    const float* b0   = (const float*)d_in[4];
    const float* W1   = (const float*)d_in[5];
    const float* b1   = (const float*)d_in[6];
    const float* W2   = (const float*)d_in[7];
    const float* b2   = (const float*)d_in[8];
    float* out = (float*)d_out;

    cudaFuncSetAttribute(k_fused, cudaFuncAttributeMaxDynamicSharedMemorySize, SMEM_TOT);

    k_transpose<<<4096, 256>>>(w);
    k_packfrag<<<128, 256>>>(W0, b0, W1, b1);
    k_fused<<<NCTAS, NTHREADS, SMEM_TOT>>>(x, cond, W2, b2, out);
    k_reduce<<<1, 64>>>(out);
}

// round 17
// speedup vs baseline: 1.4366x; 1.0289x over previous
#include <cuda_runtime.h>
#include <cuda_fp16.h>
#include <stdint.h>

// Problem dims
#define BB   64
#define TT   4096
#define NTOK (BB*TT)          // 262144
#define TOKPC 64              // tokens per CTA
#define NCTAS (NTOK/TOKPC)    // 4096
#define NTHREADS 128

// smem strides (halves): row stride in 16B units coprime with 8 -> LDSM/STSM conflict-free
#define SC  104               // comb stride (K=96 padded)
#define SHE 136               // hidden-exchange stride

// smem byte offsets (total 55808 B -> 4 CTAs/SM fits 228KB)
#define OFF_COMB   0                  // 64*SC*2  = 13312
#define OFF_HEX0   13312              // 64*SHE*2 = 17408
#define OFF_HEX1   30720              // 17408
#define OFF_BIAS   48128              // 2048 halves = 4096
#define OFF_W2     52224              // 512 floats  = 2048
#define OFF_SPS    54272              // 128 floats  = 512
#define OFF_SPT    54784              // 128 floats  = 512
#define OFF_ZA     55296              // 64 floats   = 256
#define OFF_SRED   55552              // 64 floats   = 256
#define SMEM_TOT   55808

// ---------------- device scratch ----------------
__device__ __align__(16) __half g_wT[(size_t)BB * 64 * 64 * 64]; // [b][y][x][c] fp16, 32MB
__device__ __align__(16) uint4 g_wfrag[16 * 2048];               // [li][colg][ntp][ks][lane]
__device__ __align__(4) __half g_biasH[4 * 4 * 128];             // [net][layer][n] fp16
__device__ float g_part[NCTAS];                                  // per-tile s-sums

// ---------------- helpers ----------------
__device__ __forceinline__ void mma16816(float c[4], const unsigned a0, const unsigned a1,
                                         const unsigned a2, const unsigned a3,
                                         unsigned b0, unsigned b1) {
    asm volatile(
        "mma.sync.aligned.m16n8k16.row.col.f32.f16.f16.f32 "
        "{%0,%1,%2,%3}, {%4,%5,%6,%7}, {%8,%9}, {%0,%1,%2,%3};"
        : "+f"(c[0]), "+f"(c[1]), "+f"(c[2]), "+f"(c[3])
        : "r"(a0), "r"(a1), "r"(a2), "r"(a3), "r"(b0), "r"(b1));
}

__device__ __forceinline__ void mma16816h(unsigned c[2], const unsigned a0, const unsigned a1,
                                          const unsigned a2, const unsigned a3,
                                          unsigned b0, unsigned b1) {
    asm volatile(
        "mma.sync.aligned.m16n8k16.row.col.f16.f16.f16.f16 "
        "{%0,%1}, {%2,%3,%4,%5}, {%6,%7}, {%0,%1};"
        : "+r"(c[0]), "+r"(c[1])
        : "r"(a0), "r"(a1), "r"(a2), "r"(a3), "r"(b0), "r"(b1));
}

__device__ __forceinline__ void ldsm_x4(unsigned r[4], uint32_t addr) {
    asm volatile("ldmatrix.sync.aligned.m8n8.x4.shared.b16 {%0,%1,%2,%3}, [%4];"
                 : "=r"(r[0]), "=r"(r[1]), "=r"(r[2]), "=r"(r[3]) : "r"(addr));
}

__device__ __forceinline__ void stsm_x4(uint32_t addr, unsigned r0, unsigned r1,
                                        unsigned r2, unsigned r3) {
    asm volatile("stmatrix.sync.aligned.m8n8.x4.shared.b16 [%0], {%1,%2,%3,%4};"
                 :: "r"(addr), "r"(r0), "r"(r1), "r"(r2), "r"(r3) : "memory");
}

__device__ __forceinline__ uint32_t smem_u32(const void* p) {
    uint32_t a;
    asm("{ .reg .u64 t; cvta.to.shared.u64 t, %1; cvt.u32.u64 %0, t; }" : "=r"(a) : "l"(p));
    return a;
}

__device__ __forceinline__ float fast_silu(float v) {
    float t;
    asm("tanh.approx.f32 %0, %1;" : "=f"(t) : "f"(0.5f * v));
    return 0.5f * v * (t + 1.0f);
}
__device__ __forceinline__ unsigned packh2(float a, float b) {
    __half2 h = __floats2half2_rn(a, b);
    return *(unsigned*)&h;
}
__device__ __forceinline__ __half2 silu_h2h(__half2 p) {
    __half2 u = __hmul2(p, __float2half2_rn(0.5f));
    __half2 t;
    asm("tanh.approx.f16x2 %0, %1;" : "=r"(*(unsigned*)&t) : "r"(*(unsigned*)&u));
    return __hfma2(u, t, u);
}

// ---------------- transpose w[B,C,H,W] f32 -> wT[b][y][x][c] fp16 ----------------
__global__ void k_transpose(const float* __restrict__ w) {
    __shared__ float tile[64][65];
    int bid = blockIdx.x;
    int b = bid >> 6, y = bid & 63;
    int t = threadIdx.x;
    {
        int c = t >> 2, xq = (t & 3) * 16;
        const float4* src = (const float4*)(w + ((((b << 6) | c) << 6 | y) << 6) + xq);
#pragma unroll
        for (int j = 0; j < 4; j++) {
            float4 v = src[j];
            tile[c][xq + 4 * j + 0] = v.x;
            tile[c][xq + 4 * j + 1] = v.y;
            tile[c][xq + 4 * j + 2] = v.z;
            tile[c][xq + 4 * j + 3] = v.w;
        }
    }
    __syncthreads();
    {
        int xx = t >> 2, cq = (t & 3) * 16;
        __half2* dst = (__half2*)(g_wT + ((((size_t)(((b << 6) | y)) << 6 | xx)) << 6) + cq);
#pragma unroll
        for (int j = 0; j < 8; j++)
            dst[j] = __floats2half2_rn(tile[cq + 2 * j][xx], tile[cq + 2 * j + 1][xx]);
    }
}

// ---------------- pack weights into MMA B-fragment order ----------------
__device__ __forceinline__ float getw_(const float* W0, const float* W1,
                                       int net, int layer, int n, int k) {
    if (layer == 0) {
        int oc = -1;
        if (k < 64) oc = 1 + k;
        else if (k < 80) oc = 65 + (k - 64);
        else if (k == 80) oc = 0;
        return (oc >= 0) ? W0[(net * 128 + n) * 81 + oc] : 0.f;
    }
    return W1[((net * 3 + (layer - 1)) * 128 + n) * 128 + k];
}

__global__ void k_packfrag(const float* __restrict__ W0, const float* __restrict__ b0,
                           const float* __restrict__ W1, const float* __restrict__ b1) {
    int idx = blockIdx.x * 256 + threadIdx.x;      // 0..32767
    int gi = idx >> 11;
    int rem = idx & 2047;
    int lane = rem & 31;
    int ks = (rem >> 5) & 7;
    int ntp = (rem >> 8) & 3;
    int colg = (rem >> 10) & 1;
    int net = gi >> 2, layer = gi & 3;
    int gid = lane >> 2, tig = lane & 3;
    int n_even = colg * 64 + ntp * 16 + gid;
    int n_odd  = n_even + 8;
    int k0 = ks * 16 + tig * 2;
    uint4 v;
    v.x = packh2(getw_(W0, W1, net, layer, n_even, k0),     getw_(W0, W1, net, layer, n_even, k0 + 1));
    v.y = packh2(getw_(W0, W1, net, layer, n_even, k0 + 8), getw_(W0, W1, net, layer, n_even, k0 + 9));
    v.z = packh2(getw_(W0, W1, net, layer, n_odd,  k0),     getw_(W0, W1, net, layer, n_odd,  k0 + 1));
    v.w = packh2(getw_(W0, W1, net, layer, n_odd,  k0 + 8), getw_(W0, W1, net, layer, n_odd,  k0 + 9));
    g_wfrag[idx] = v;
    if (idx < 2048) {
        int bn = idx >> 9, bl = (idx >> 7) & 3, bb_ = idx & 127;
        float bv = (bl == 0) ? b0[bn * 128 + bb_]
                             : b1[((bn * 3 + bl - 1) * 128) + bb_];
        g_biasH[idx] = __float2half_rn(bv);
    }
}

// ---------------- fused two-pass coupling kernel: 64 tok/CTA, 4 CTAs/SM, ping-pong hEx ----------------
__global__ void __launch_bounds__(NTHREADS, 4) k_fused(
    const float* __restrict__ x, const float* __restrict__ cond,
    const float* __restrict__ W2, const float* __restrict__ b2,
    float* __restrict__ out) {
    extern __shared__ __align__(16) char smraw[];
    __half* combS  = (__half*)(smraw + OFF_COMB);
    __half* sbiasH = (__half*)(smraw + OFF_BIAS);
    float*  w2s    = (float*)(smraw + OFF_W2);
    float*  spartS = (float*)(smraw + OFF_SPS);
    float*  spartT = (float*)(smraw + OFF_SPT);
    float*  zA     = (float*)(smraw + OFF_ZA);
    float*  sred   = (float*)(smraw + OFF_SRED);

    int tid = threadIdx.x;
    int wid = tid >> 5, lane = tid & 31;
    int gid = lane >> 2, tig = lane & 3;
    int rowg = wid & 1;          // 2 row-groups x 32 tokens = 64
    int colg = wid >> 1;         // 2 col-groups x 64 cols
    int tile = blockIdx.x;

    uint32_t combA = smem_u32(combS);
    uint32_t hexA[2] = {smem_u32(smraw + OFF_HEX0), smem_u32(smraw + OFF_HEX1)};

    // stage biases (all 16 layers) + w2 (all 4 nets)
#pragma unroll
    for (int i = 0; i < 8; i++)
        ((unsigned*)sbiasH)[tid + i * 128] = ((const unsigned*)g_biasH)[tid + i * 128];
#pragma unroll
    for (int i = 0; i < 4; i++)
        w2s[tid + i * 128] = __ldg(&W2[tid + i * 128]);

    // ldmatrix per-thread offsets
    int aRow = lane & 15;
    int aK   = (lane >> 4) * 8;
    // stmatrix per-thread offsets: tile i <- lanes 8i..8i+7
    int sti = lane >> 3, str = lane & 7;
    int stRowOff = (sti & 1) * 8;
    int stColOff = (sti >> 1) * 8;

    unsigned aPack[2][8][2];
    int lastw = 1;   // next hEx write goes to lastw^1

    for (int ps = 0; ps < 2; ps++) {
        // ===== gather + build comb (2 threads per token, LDG.128) =====
        {
            int tk = tid >> 1, p = tid & 1;
            int g0 = tile * TOKPC + tk;
            int b = g0 >> 12;
            float zy = __ldg(&x[g0 * 2 + 1]);
            float zx = (ps == 0) ? __ldg(&x[g0 * 2]) : zA[tk];
            float zkeep = (ps == 0) ? zy : zx;
            float ix = zx * 63.f, iy = zy * 63.f;
            float ix0 = floorf(ix), iy0 = floorf(iy);
            float wx1 = ix - ix0, wx0 = 1.f - wx1;
            float wy1 = iy - iy0, wy0 = 1.f - wy1;
            float acc[32];
#pragma unroll
            for (int i = 0; i < 32; i++) acc[i] = 0.f;
            float cxs[4] = {ix0, ix0 + 1.f, ix0, ix0 + 1.f};
            float cys[4] = {iy0, iy0, iy0 + 1.f, iy0 + 1.f};
            float cws[4] = {wy0 * wx0, wy0 * wx1, wy1 * wx0, wy1 * wx1};
#pragma unroll
            for (int cr = 0; cr < 4; cr++) {
                float xf = cxs[cr], yf = cys[cr], wt = cws[cr];
                if (xf >= 0.f && xf <= 63.f && yf >= 0.f && yf <= 63.f) {
                    int xi = (int)xf, yi = (int)yf;
                    const uint4* src = (const uint4*)((const char*)g_wT +
                        (((size_t)(((b << 6) | yi) << 6 | xi)) << 7) + (p << 6));
#pragma unroll
                    for (int u = 0; u < 4; u++) {
                        uint4 v = __ldg(src + u);
                        unsigned ww[4] = {v.x, v.y, v.z, v.w};
#pragma unroll
                        for (int q = 0; q < 4; q++) {
                            float2 f = __half22float2(*(__half2*)&ww[q]);
                            acc[u * 8 + 2 * q]     += wt * f.x;
                            acc[u * 8 + 2 * q + 1] += wt * f.y;
                        }
                    }
                }
            }
            uint4* dst = (uint4*)((char*)combS + tk * (SC * 2) + p * 64);
#pragma unroll
            for (int u = 0; u < 4; u++) {
                uint4 o;
                o.x = packh2(acc[u * 8 + 0], acc[u * 8 + 1]);
                o.y = packh2(acc[u * 8 + 2], acc[u * 8 + 3]);
                o.z = packh2(acc[u * 8 + 4], acc[u * 8 + 5]);
                o.w = packh2(acc[u * 8 + 6], acc[u * 8 + 7]);
                dst[u] = o;
            }
            __half* crow = combS + tk * SC;
            if (p == 0) {
#pragma unroll
                for (int i = 0; i < 16; i++)
                    crow[64 + i] = __float2half_rn(__ldg(&cond[b * 16 + i]));
                crow[80] = __float2half_rn(zkeep);
#pragma unroll
                for (int cc = 81; cc < 88; cc++) crow[cc] = __float2half_rn(0.f);
            } else {
#pragma unroll
                for (int cc = 88; cc < 96; cc++) crow[cc] = __float2half_rn(0.f);
            }
        }
        __syncthreads();   // comb visible

        // ===== 8 layers of this pass (ping-pong hEx, 1 sync/layer) =====
        for (int l = 0; l < 8; l++) {
            int li = ps * 8 + l;
            const uint4* wfB = g_wfrag + ((size_t)li << 11) + (colg << 10) + lane;
            const __half* lbH = sbiasH + li * 128 + 64 * colg;
            int hr = lastw;          // buffer to read (last written)
            int hw = lastw ^ 1;      // buffer to write

            if (l < 4) {
                // ================= s-net: fp32 accumulate =================
                float acc[2][8][4];
#pragma unroll
                for (int mt = 0; mt < 2; mt++)
#pragma unroll
                    for (int nt = 0; nt < 8; nt++)
#pragma unroll
                        for (int q = 0; q < 4; q++) acc[mt][nt][q] = 0.f;

                if (l == 0) {
                    uint32_t a0 = combA + ((32 * rowg + aRow) * SC + aK) * 2;
                    uint32_t a1 = a0 + 16 * SC * 2;
#pragma unroll
                    for (int ks = 0; ks < 6; ks++) {
                        unsigned af0[4], af1[4];
                        ldsm_x4(af0, a0 + ks * 32);
                        ldsm_x4(af1, a1 + ks * 32);
#pragma unroll
                        for (int ntp = 0; ntp < 4; ntp++) {
                            uint4 bf = __ldg(wfB + (ntp * 8 + ks) * 32);
                            mma16816(acc[0][2 * ntp],     af0[0], af0[1], af0[2], af0[3], bf.x, bf.y);
                            mma16816(acc[0][2 * ntp + 1], af0[0], af0[1], af0[2], af0[3], bf.z, bf.w);
                            mma16816(acc[1][2 * ntp],     af1[0], af1[1], af1[2], af1[3], bf.x, bf.y);
                            mma16816(acc[1][2 * ntp + 1], af1[0], af1[1], af1[2], af1[3], bf.z, bf.w);
                        }
                    }
                } else {
                    int pc = colg ^ 1;
                    uint32_t pbase = hexA[hr] + ((32 * rowg + aRow) * SHE + 64 * pc + aK) * 2;
                    int pks0 = 4 * pc, oks0 = 4 * colg;
#pragma unroll
                    for (int q = 0; q < 4; q++) {
                        unsigned af0[4], af1[4];
                        ldsm_x4(af0, pbase + q * 32);
                        ldsm_x4(af1, pbase + 16 * SHE * 2 + q * 32);
#pragma unroll
                        for (int ntp = 0; ntp < 4; ntp++) {
                            uint4 bf = __ldg(wfB + (ntp * 8 + pks0 + q) * 32);
                            mma16816(acc[0][2 * ntp],     af0[0], af0[1], af0[2], af0[3], bf.x, bf.y);
                            mma16816(acc[0][2 * ntp + 1], af0[0], af0[1], af0[2], af0[3], bf.z, bf.w);
                            mma16816(acc[1][2 * ntp],     af1[0], af1[1], af1[2], af1[3], bf.x, bf.y);
                            mma16816(acc[1][2 * ntp + 1], af1[0], af1[1], af1[2], af1[3], bf.z, bf.w);
                        }
                    }
#pragma unroll
                    for (int q = 0; q < 4; q++) {
#pragma unroll
                        for (int ntp = 0; ntp < 4; ntp++) {
                            uint4 bf = __ldg(wfB + (ntp * 8 + oks0 + q) * 32);
                            mma16816(acc[0][2 * ntp], aPack[0][2 * q][0], aPack[0][2 * q][1],
                                     aPack[0][2 * q + 1][0], aPack[0][2 * q + 1][1], bf.x, bf.y);
                            mma16816(acc[0][2 * ntp + 1], aPack[0][2 * q][0], aPack[0][2 * q][1],
                                     aPack[0][2 * q + 1][0], aPack[0][2 * q + 1][1], bf.z, bf.w);
                            mma16816(acc[1][2 * ntp], aPack[1][2 * q][0], aPack[1][2 * q][1],
                                     aPack[1][2 * q + 1][0], aPack[1][2 * q + 1][1], bf.x, bf.y);
                            mma16816(acc[1][2 * ntp + 1], aPack[1][2 * q][0], aPack[1][2 * q][1],
                                     aPack[1][2 * q + 1][0], aPack[1][2 * q + 1][1], bf.z, bf.w);
                        }
                    }
                }

                if (l == 3) {
                    const float* w2 = w2s + ps * 256 + 64 * colg;
#pragma unroll
                    for (int mt = 0; mt < 2; mt++) {
                        float p0 = 0.f, p1 = 0.f;
#pragma unroll
                        for (int nt = 0; nt < 8; nt++) {
                            int c = nt * 8 + tig * 2;
                            float2 bf2 = __half22float2(*(const __half2*)(lbH + c));
                            float w0 = w2[c], w1 = w2[c + 1];
                            p0 += fast_silu(acc[mt][nt][0] + bf2.x) * w0
                                + fast_silu(acc[mt][nt][1] + bf2.y) * w1;
                            p1 += fast_silu(acc[mt][nt][2] + bf2.x) * w0
                                + fast_silu(acc[mt][nt][3] + bf2.y) * w1;
                        }
                        p0 += __shfl_xor_sync(0xffffffffu, p0, 1);
                        p0 += __shfl_xor_sync(0xffffffffu, p0, 2);
                        p1 += __shfl_xor_sync(0xffffffffu, p1, 1);
                        p1 += __shfl_xor_sync(0xffffffffu, p1, 2);
                        if (tig == 0) {
                            spartS[colg * 64 + 32 * rowg + 16 * mt + gid]     = p0;
                            spartS[colg * 64 + 32 * rowg + 16 * mt + gid + 8] = p1;
                        }
                    }
                } else {
#pragma unroll
                    for (int mt = 0; mt < 2; mt++) {
#pragma unroll
                        for (int nt = 0; nt < 8; nt++) {
                            float2 bf2 = __half22float2(*(const __half2*)(lbH + nt * 8 + tig * 2));
                            aPack[mt][nt][0] = packh2(fast_silu(acc[mt][nt][0] + bf2.x),
                                                      fast_silu(acc[mt][nt][1] + bf2.y));
                            aPack[mt][nt][1] = packh2(fast_silu(acc[mt][nt][2] + bf2.x),
                                                      fast_silu(acc[mt][nt][3] + bf2.y));
                        }
                        uint32_t sa = hexA[hw] +
                            ((32 * rowg + 16 * mt + stRowOff + str) * SHE + 64 * colg + stColOff) * 2;
#pragma unroll
                        for (int p = 0; p < 4; p++)
                            stsm_x4(sa + p * 32, aPack[mt][2 * p][0], aPack[mt][2 * p][1],
                                    aPack[mt][2 * p + 1][0], aPack[mt][2 * p + 1][1]);
                    }
                    lastw = hw;
                }
            } else {
                // ================= t-net: fp16 accumulate =================
                unsigned acch[2][8][2];
#pragma unroll
                for (int mt = 0; mt < 2; mt++)
#pragma unroll
                    for (int nt = 0; nt < 8; nt++) { acch[mt][nt][0] = 0u; acch[mt][nt][1] = 0u; }

                if (l == 4) {
                    uint32_t a0 = combA + ((32 * rowg + aRow) * SC + aK) * 2;
                    uint32_t a1 = a0 + 16 * SC * 2;
#pragma unroll
                    for (int ks = 0; ks < 6; ks++) {
                        unsigned af0[4], af1[4];
                        ldsm_x4(af0, a0 + ks * 32);
                        ldsm_x4(af1, a1 + ks * 32);
#pragma unroll
                        for (int ntp = 0; ntp < 4; ntp++) {
                            uint4 bf = __ldg(wfB + (ntp * 8 + ks) * 32);
                            mma16816h(acch[0][2 * ntp],     af0[0], af0[1], af0[2], af0[3], bf.x, bf.y);
                            mma16816h(acch[0][2 * ntp + 1], af0[0], af0[1], af0[2], af0[3], bf.z, bf.w);
                            mma16816h(acch[1][2 * ntp],     af1[0], af1[1], af1[2], af1[3], bf.x, bf.y);
                            mma16816h(acch[1][2 * ntp + 1], af1[0], af1[1], af1[2], af1[3], bf.z, bf.w);
                        }
                    }
                } else {
                    int pc = colg ^ 1;
                    uint32_t pbase = hexA[hr] + ((32 * rowg + aRow) * SHE + 64 * pc + aK) * 2;
                    int pks0 = 4 * pc, oks0 = 4 * colg;
#pragma unroll
                    for (int q = 0; q < 4; q++) {
                        unsigned af0[4], af1[4];
                        ldsm_x4(af0, pbase + q * 32);
                        ldsm_x4(af1, pbase + 16 * SHE * 2 + q * 32);
#pragma unroll
                        for (int ntp = 0; ntp < 4; ntp++) {
                            uint4 bf = __ldg(wfB + (ntp * 8 + pks0 + q) * 32);
                            mma16816h(acch[0][2 * ntp],     af0[0], af0[1], af0[2], af0[3], bf.x, bf.y);
                            mma16816h(acch[0][2 * ntp + 1], af0[0], af0[1], af0[2], af0[3], bf.z, bf.w);
                            mma16816h(acch[1][2 * ntp],     af1[0], af1[1], af1[2], af1[3], bf.x, bf.y);
                            mma16816h(acch[1][2 * ntp + 1], af1[0], af1[1], af1[2], af1[3], bf.z, bf.w);
                        }
                    }
#pragma unroll
                    for (int q = 0; q < 4; q++) {
#pragma unroll
                        for (int ntp = 0; ntp < 4; ntp++) {
                            uint4 bf = __ldg(wfB + (ntp * 8 + oks0 + q) * 32);
                            mma16816h(acch[0][2 * ntp], aPack[0][2 * q][0], aPack[0][2 * q][1],
                                      aPack[0][2 * q + 1][0], aPack[0][2 * q + 1][1], bf.x, bf.y);
                            mma16816h(acch[0][2 * ntp + 1], aPack[0][2 * q][0], aPack[0][2 * q][1],
                                      aPack[0][2 * q + 1][0], aPack[0][2 * q + 1][1], bf.z, bf.w);
                            mma16816h(acch[1][2 * ntp], aPack[1][2 * q][0], aPack[1][2 * q][1],
                                      aPack[1][2 * q + 1][0], aPack[1][2 * q + 1][1], bf.x, bf.y);
                            mma16816h(acch[1][2 * ntp + 1], aPack[1][2 * q][0], aPack[1][2 * q][1],
                                      aPack[1][2 * q + 1][0], aPack[1][2 * q + 1][1], bf.z, bf.w);
                        }
                    }
                }

                if (l == 7) {
                    const float* w2 = w2s + ps * 256 + 128 + 64 * colg;
#pragma unroll
                    for (int mt = 0; mt < 2; mt++) {
                        float p0 = 0.f, p1 = 0.f;
#pragma unroll
                        for (int nt = 0; nt < 8; nt++) {
                            int c = nt * 8 + tig * 2;
                            __half2 bias = *(const __half2*)(lbH + c);
                            float w0 = w2[c], w1 = w2[c + 1];
                            float2 f0 = __half22float2(silu_h2h(__hadd2(*(__half2*)&acch[mt][nt][0], bias)));
                            float2 f1 = __half22float2(silu_h2h(__hadd2(*(__half2*)&acch[mt][nt][1], bias)));
                            p0 += f0.x * w0 + f0.y * w1;
                            p1 += f1.x * w0 + f1.y * w1;
                        }
                        p0 += __shfl_xor_sync(0xffffffffu, p0, 1);
                        p0 += __shfl_xor_sync(0xffffffffu, p0, 2);
                        p1 += __shfl_xor_sync(0xffffffffu, p1, 1);
                        p1 += __shfl_xor_sync(0xffffffffu, p1, 2);
                        if (tig == 0) {
                            spartT[colg * 64 + 32 * rowg + 16 * mt + gid]     = p0;
                            spartT[colg * 64 + 32 * rowg + 16 * mt + gid + 8] = p1;
                        }
                    }
                } else {
#pragma unroll
                    for (int mt = 0; mt < 2; mt++) {
#pragma unroll
                        for (int nt = 0; nt < 8; nt++) {
                            __half2 bias = *(const __half2*)(lbH + nt * 8 + tig * 2);
                            __half2 h0 = silu_h2h(__hadd2(*(__half2*)&acch[mt][nt][0], bias));
                            __half2 h1 = silu_h2h(__hadd2(*(__half2*)&acch[mt][nt][1], bias));
                            aPack[mt][nt][0] = *(unsigned*)&h0;
                            aPack[mt][nt][1] = *(unsigned*)&h1;
                        }
                        uint32_t sa = hexA[hw] +
                            ((32 * rowg + 16 * mt + stRowOff + str) * SHE + 64 * colg + stColOff) * 2;
#pragma unroll
                        for (int p = 0; p < 4; p++)
                            stsm_x4(sa + p * 32, aPack[mt][2 * p][0], aPack[mt][2 * p][1],
                                    aPack[mt][2 * p + 1][0], aPack[mt][2 * p + 1][1]);
                    }
                    lastw = hw;
                }
            }

            __syncthreads();   // publishes hEx[hw]; guarantees hEx[hr] reads done
        }

        // ===== coupling epilogue for this pass =====
        if (tid < TOKPC) {
            int g0 = tile * TOKPC + tid;
            float zold = (ps == 0) ? __ldg(&x[g0 * 2]) : __ldg(&x[g0 * 2 + 1]);
            float s_lin = spartS[tid] + spartS[64 + tid] + __ldg(&b2[ps * 2]);
            float t_lin = spartT[tid] + spartT[64 + tid] + __ldg(&b2[ps * 2 + 1]);
            float sv = tanhf(s_lin) * 1.5f;
            float z = zold * __expf(sv) + t_lin;
            out[g0 * 2 + ps] = z;
            if (ps == 0) { zA[tid] = z; sred[tid] = sv; }
            else sred[tid] += sv;
        }
        __syncthreads();
    }

    // ===== deterministic block reduce of s (both passes) =====
    if (tid < 32) {
        float v = sred[tid] + sred[tid + 32];
#pragma unroll
        for (int off = 16; off; off >>= 1) v += __shfl_xor_sync(0xffffffffu, v, off);
        if (tid == 0) g_part[tile] = v;
    }
}

// ---------------- log-det reduce ----------------
__global__ void k_reduce(float* __restrict__ out) {
    int b = threadIdx.x;
    if (b < BB) {
        float acc = 0.f;
        for (int i = 0; i < 64; i++)
            acc += g_part[b * 64 + i];
        out[(size_t)NTOK * 2 + b] = acc;
    }
}

// ---------------- launcher ----------------
extern "C" void kernel_launch(void* const* d_in, const int* in_sizes, int n_in,
                              void* d_out, int out_size) {
    const float* x    = (const float*)d_in[0];
    const float* w    = (const float*)d_in[1];
    const float* cond = (const float*)d_in[2];
    const float* W0   = (const float*)d_in[3];
    const float* b0   = (const float*)d_in[4];
    const float* W1   = (const float*)d_in[5];
    const float* b1   = (const float*)d_in[6];
    const float* W2   = (const float*)d_in[7];
    const float* b2   = (const float*)d_in[8];
    float* out = (float*)d_out;

    cudaFuncSetAttribute(k_fused, cudaFuncAttributeMaxDynamicSharedMemorySize, SMEM_TOT);

    k_transpose<<<4096, 256>>>(w);
    k_packfrag<<<128, 256>>>(W0, b0, W1, b1);
    k_fused<<<NCTAS, NTHREADS, SMEM_TOT>>>(x, cond, W2, b2, out);
    k_reduce<<<1, 64>>>(out);
}